// round 15
// baseline (speedup 1.0000x reference)
#include <cuda_runtime.h>
#include <cuda_bf16.h>
#include <cstdint>

#define NN 50000
#define EE 800000
#define DIN 256
#define HH 128
#define AA 32

// ---------------- scratch (device globals) ----------------
__device__ float g_h   [(size_t)NN * HH];
__device__ float g_h0  [(size_t)NN * HH];
__device__ float g_h2  [(size_t)NN * HH];
__device__ float g_esrc[NN];
__device__ float g_edst[NN];
__device__ float g_wa_src[DIN];
__device__ float g_wa_dst[DIN];
__device__ int   g_rowcnt[NN];
__device__ int   g_rowoff[NN + 1];
__device__ int   g_cursor[NN];
__device__ int   g_csr_src[EE];
__device__ float g_csr_e[EE];
__device__ float g_stats0[2 * HH];
__device__ float g_stats2[2 * HH];
// packed bf16 hi/lo weight planes. W: kp 0..127 | W1: +16384 | W2: +24576
__device__ __align__(16) uint2 g_Bw[32768];
__device__ int   g_is64;

#define OFF_W1 16384
#define OFF_W2 24576

// ---------------- helpers ----------------
__device__ __forceinline__ uint2 bf16_split_pack(float v0, float v1) {
    __nv_bfloat16 h0 = __float2bfloat16_rn(v0);
    __nv_bfloat16 h1 = __float2bfloat16_rn(v1);
    float r0 = v0 - __bfloat162float(h0);
    float r1 = v1 - __bfloat162float(h1);
    __nv_bfloat16 l0 = __float2bfloat16_rn(r0);
    __nv_bfloat16 l1 = __float2bfloat16_rn(r1);
    uint2 w;
    w.x = (uint32_t)__bfloat16_as_ushort(h0) | ((uint32_t)__bfloat16_as_ushort(h1) << 16);
    w.y = (uint32_t)__bfloat16_as_ushort(l0) | ((uint32_t)__bfloat16_as_ushort(l1) << 16);
    return w;
}
__device__ __forceinline__ void mma_bf16(float* c, const unsigned* a, unsigned b0, unsigned b1) {
    asm volatile(
        "mma.sync.aligned.m16n8k16.row.col.f32.bf16.bf16.f32 "
        "{%0,%1,%2,%3}, {%4,%5,%6,%7}, {%8,%9}, {%0,%1,%2,%3};"
        : "+f"(c[0]), "+f"(c[1]), "+f"(c[2]), "+f"(c[3])
        : "r"(a[0]), "r"(a[1]), "r"(a[2]), "r"(a[3]), "r"(b0), "r"(b1));
}
__device__ __forceinline__ void cp16(uint32_t saddr, const void* gaddr) {
    asm volatile("cp.async.ca.shared.global [%0], [%1], 16;" :: "r"(saddr), "l"(gaddr));
}

// ---------------- init (+dtype detect) + fused W@a GEMVs ----------------
// blocks 0..195: zero-init; blocks 196..451: wa row (k = b-196)
__global__ void k_init(const int* ei_words, const float* __restrict__ W,
                       const float* __restrict__ a_src, const float* __restrict__ a_dst) {
    int b = blockIdx.x;
    if (b < 196) {
        int idx = b * 256 + threadIdx.x;
        if (idx == 0) {
            int nz = 0;
            for (int i = 1; i < 2048; i += 2) nz += (ei_words[i] != 0);
            g_is64 = (nz == 0) ? 1 : 0;
        }
        if (idx < NN) g_rowcnt[idx] = 0;
        if (idx < 2 * HH) { g_stats0[idx] = 0.f; g_stats2[idx] = 0.f; }
    } else {
        __shared__ float ss[4], sd[4];
        int k = b - 196;         // 0..255
        int t = threadIdx.x;
        float s = 0.f, d = 0.f;
        if (t < 128) {
            float w = W[(size_t)k * HH + t];
            s = w * a_src[t];
            d = w * a_dst[t];
        }
#pragma unroll
        for (int o = 16; o; o >>= 1) {
            s += __shfl_xor_sync(0xffffffffu, s, o);
            d += __shfl_xor_sync(0xffffffffu, d, o);
        }
        if (t < 128 && (t & 31) == 0) { ss[t >> 5] = s; sd[t >> 5] = d; }
        __syncthreads();
        if (t == 0) g_wa_src[k] = ss[0] + ss[1] + ss[2] + ss[3];
        if (t == 1) g_wa_dst[k] = sd[0] + sd[1] + sd[2] + sd[3];
    }
}

// e_src[n] = x[n]·wa_src, e_dst[n] = x[n]·wa_dst  (warp per node)
__global__ void k_edot(const float* __restrict__ x) {
    int lane = threadIdx.x & 31;
    int n = blockIdx.x * 8 + (threadIdx.x >> 5);
    if (n >= NN) return;
    const float4* xr = (const float4*)(x + (size_t)n * DIN);
    const float4* ws = (const float4*)g_wa_src;
    const float4* wd = (const float4*)g_wa_dst;
    float4 x0 = xr[lane], x1 = xr[lane + 32];
    float4 s0 = ws[lane], s1 = ws[lane + 32];
    float4 d0 = wd[lane], d1 = wd[lane + 32];
    float s = x0.x * s0.x + x0.y * s0.y + x0.z * s0.z + x0.w * s0.w
            + x1.x * s1.x + x1.y * s1.y + x1.z * s1.z + x1.w * s1.w;
    float d = x0.x * d0.x + x0.y * d0.y + x0.z * d0.z + x0.w * d0.w
            + x1.x * d1.x + x1.y * d1.y + x1.z * d1.z + x1.w * d1.w;
#pragma unroll
    for (int o = 16; o; o >>= 1) {
        s += __shfl_xor_sync(0xffffffffu, s, o);
        d += __shfl_xor_sync(0xffffffffu, d, o);
    }
    if (lane == 0) { g_esrc[n] = s; g_edst[n] = d; }
}

// split all weights into packed bf16 hi/lo k-pair words
__global__ void k_splitW(const float* __restrict__ W, const float* __restrict__ W1,
                         const float* __restrict__ W2) {
    int i = blockIdx.x * 256 + threadIdx.x;
    if (i >= 32768) return;
    const float* src; int base;
    if (i < OFF_W1) { src = W;  base = i; }
    else if (i < OFF_W2) { src = W1; base = i - OFF_W1; }
    else { src = W2; base = i - OFF_W2; }
    int kp = base >> 7, n = base & 127;
    float v0 = src[(size_t)(2 * kp) * HH + n];
    float v1 = src[(size_t)(2 * kp + 1) * HH + n];
    g_Bw[i] = bf16_split_pack(v0, v1);
}

// ------------- 3xBF16 tensor-core GEMM, M-tile 64 (3 CTAs/SM) -------------
#define GBM 64
#define GBN 128
#define ASROW 68
#define BSROW 132

__global__ __launch_bounds__(256, 3) void k_gemm_bf16(
    const float* __restrict__ A, const uint2* __restrict__ Bw,
    float* __restrict__ C, int M, int K)
{
    extern __shared__ uint2 smem[];
    uint2 (*As)[8][ASROW] = reinterpret_cast<uint2 (*)[8][ASROW]>(smem);
    uint2 (*Bs)[8][BSROW] = reinterpret_cast<uint2 (*)[8][BSROW]>(smem + 16 * ASROW);

    const int tid = threadIdx.x;
    const int warp = tid >> 5, lane = tid & 31;
    const int g = lane >> 2, q = lane & 3;
    const int wm = (warp & 1) * 32;
    const int wn = (warp >> 1) * 32;
    const int blockRow = blockIdx.x * GBM;

    const int arow = tid >> 2;
    const int acol = (tid & 3) * 4;
    const int bkp = tid >> 5;
    const int bnn = lane * 4;

    const int aRowG = blockRow + arow;
    const bool aValid = aRowG < M;

    float c[2][4][4];
#pragma unroll
    for (int mt = 0; mt < 2; mt++)
#pragma unroll
        for (int nt = 0; nt < 4; nt++)
#pragma unroll
            for (int j = 0; j < 4; j++) c[mt][nt][j] = 0.f;

    float av[4];

    {
        uint32_t sB = (uint32_t)__cvta_generic_to_shared(&Bs[0][bkp][bnn]);
        const uint2* gB = Bw + (size_t)bkp * GBN + bnn;
        cp16(sB, gB); cp16(sB + 16, gB + 2);
        asm volatile("cp.async.commit_group;");

#pragma unroll
        for (int j = 0; j < 4; j++) av[j] = 0.f;
        if (aValid) {
            float4 v = *(const float4*)&A[(long)aRowG * K + acol];
            av[0] = v.x; av[1] = v.y; av[2] = v.z; av[3] = v.w;
        }
        As[0][(acol >> 1) + 0][arow] = bf16_split_pack(av[0], av[1]);
        As[0][(acol >> 1) + 1][arow] = bf16_split_pack(av[2], av[3]);
        asm volatile("cp.async.wait_group 0;" ::: "memory");
        __syncthreads();
    }

    const int ntiles = K / 16;
    for (int t = 0; t < ntiles; t++) {
        const int cur = t & 1, nxt = cur ^ 1;
        const bool more = (t + 1 < ntiles);
        if (more) {
            const int k0 = (t + 1) * 16;
            uint32_t sB = (uint32_t)__cvta_generic_to_shared(&Bs[nxt][bkp][bnn]);
            const uint2* gB = Bw + (size_t)((k0 >> 1) + bkp) * GBN + bnn;
            cp16(sB, gB); cp16(sB + 16, gB + 2);
            asm volatile("cp.async.commit_group;");

#pragma unroll
            for (int j = 0; j < 4; j++) av[j] = 0.f;
            if (aValid) {
                float4 v = *(const float4*)&A[(long)aRowG * K + k0 + acol];
                av[0] = v.x; av[1] = v.y; av[2] = v.z; av[3] = v.w;
            }
        }

        unsigned ah[2][4], al[2][4];
#pragma unroll
        for (int mt = 0; mt < 2; mt++) {
            int m = wm + mt * 16;
            uint2 A0 = As[cur][q][m + g];
            uint2 A1 = As[cur][q][m + g + 8];
            uint2 A2 = As[cur][q + 4][m + g];
            uint2 A3 = As[cur][q + 4][m + g + 8];
            ah[mt][0] = A0.x; ah[mt][1] = A1.x; ah[mt][2] = A2.x; ah[mt][3] = A3.x;
            al[mt][0] = A0.y; al[mt][1] = A1.y; al[mt][2] = A2.y; al[mt][3] = A3.y;
        }
#pragma unroll
        for (int nt = 0; nt < 4; nt++) {
            int n = wn + nt * 8 + g;
            uint2 B0 = Bs[cur][q][n];
            uint2 B1 = Bs[cur][q + 4][n];
#pragma unroll
            for (int mt = 0; mt < 2; mt++) {
                mma_bf16(c[mt][nt], ah[mt], B0.x, B1.x);
                mma_bf16(c[mt][nt], al[mt], B0.x, B1.x);
                mma_bf16(c[mt][nt], ah[mt], B0.y, B1.y);
            }
        }

        if (more) {
            As[nxt][(acol >> 1) + 0][arow] = bf16_split_pack(av[0], av[1]);
            As[nxt][(acol >> 1) + 1][arow] = bf16_split_pack(av[2], av[3]);
            asm volatile("cp.async.wait_group 0;" ::: "memory");
            __syncthreads();
        }
    }

#pragma unroll
    for (int mt = 0; mt < 2; mt++) {
#pragma unroll
        for (int nt = 0; nt < 4; nt++) {
            int col = wn + nt * 8 + q * 2;
#pragma unroll
            for (int half = 0; half < 2; half++) {
                int row = blockRow + wm + mt * 16 + g + half * 8;
                if (row < M) {
                    float2 o;
                    o.x = c[mt][nt][half * 2 + 0];
                    o.y = c[mt][nt][half * 2 + 1];
                    *(float2*)&C[(long)row * GBN + col] = o;
                }
            }
        }
    }
}

// ------------- fused fc1+fc2, M-tile 64 (+bn0 finalize, +bn2 stats) -------------
__global__ __launch_bounds__(256, 3) void k_fc12(
    const float* __restrict__ h0, const uint2* __restrict__ Bw1, const uint2* __restrict__ Bw2,
    float* __restrict__ h2, int M,
    const float* __restrict__ stats0,
    const float* __restrict__ g0, const float* __restrict__ beta0,
    const float* __restrict__ b1, const float* __restrict__ b2,
    float* __restrict__ stats2)
{
    extern __shared__ uint2 smem[];
    uint2 (*As)[8][ASROW] = reinterpret_cast<uint2 (*)[8][ASROW]>(smem);
    uint2 (*Bs)[8][BSROW] = reinterpret_cast<uint2 (*)[8][BSROW]>(smem + 16 * ASROW);
    uint2 (*Ts)[ASROW]    = reinterpret_cast<uint2 (*)[ASROW]>(smem + 16 * ASROW + 16 * BSROW);
    __shared__ float s_sum[HH];
    __shared__ float s_sq[HH];
    __shared__ float s_scale[HH];
    __shared__ float s_shift[HH];

    const int tid = threadIdx.x;
    const int warp = tid >> 5, lane = tid & 31;
    const int g = lane >> 2, q = lane & 3;
    const int wm = (warp & 1) * 32;
    const int wn = (warp >> 1) * 32;
    const int blockRow = blockIdx.x * GBM;

    const int arow = tid >> 2;
    const int acol = (tid & 3) * 4;
    const int bkp = tid >> 5;
    const int bnn = lane * 4;

    const int aRowG = blockRow + arow;
    const bool aValid = aRowG < M;

    if (tid < HH) {
        s_sum[tid] = 0.f; s_sq[tid] = 0.f;
        float mu = stats0[tid] / (float)NN;
        float var = stats0[HH + tid] / (float)NN - mu * mu;
        float sc = g0[tid] * rsqrtf(var + 1e-5f);
        s_scale[tid] = sc;
        s_shift[tid] = beta0[tid] - mu * sc;
    }
    __syncthreads();

    float c[2][4][4];
#pragma unroll
    for (int mt = 0; mt < 2; mt++)
#pragma unroll
        for (int nt = 0; nt < 4; nt++)
#pragma unroll
            for (int j = 0; j < 4; j++) c[mt][nt][j] = 0.f;

    float av[4];

    // ================= phase 1: T = relu(bn0(h0)@W1 + b1) =================
    {
        uint32_t sB = (uint32_t)__cvta_generic_to_shared(&Bs[0][bkp][bnn]);
        const uint2* gB = Bw1 + (size_t)bkp * GBN + bnn;
        cp16(sB, gB); cp16(sB + 16, gB + 2);
        asm volatile("cp.async.commit_group;");

#pragma unroll
        for (int j = 0; j < 4; j++) av[j] = 0.f;
        if (aValid) {
            float4 v = *(const float4*)&h0[(long)aRowG * HH + acol];
            av[0] = v.x; av[1] = v.y; av[2] = v.z; av[3] = v.w;
        }
#pragma unroll
        for (int j = 0; j < 4; j++)
            av[j] = fmaf(av[j], s_scale[acol + j], s_shift[acol + j]);
        As[0][(acol >> 1) + 0][arow] = bf16_split_pack(av[0], av[1]);
        As[0][(acol >> 1) + 1][arow] = bf16_split_pack(av[2], av[3]);
        asm volatile("cp.async.wait_group 0;" ::: "memory");
        __syncthreads();
    }

    for (int t = 0; t < 8; t++) {
        const int cur = t & 1, nxt = cur ^ 1;
        const bool more = (t + 1 < 8);
        if (more) {
            const int k0 = (t + 1) * 16;
            uint32_t sB = (uint32_t)__cvta_generic_to_shared(&Bs[nxt][bkp][bnn]);
            const uint2* gB = Bw1 + (size_t)((k0 >> 1) + bkp) * GBN + bnn;
            cp16(sB, gB); cp16(sB + 16, gB + 2);
            asm volatile("cp.async.commit_group;");

#pragma unroll
            for (int j = 0; j < 4; j++) av[j] = 0.f;
            if (aValid) {
                float4 v = *(const float4*)&h0[(long)aRowG * HH + k0 + acol];
                av[0] = v.x; av[1] = v.y; av[2] = v.z; av[3] = v.w;
            }
#pragma unroll
            for (int j = 0; j < 4; j++)
                av[j] = fmaf(av[j], s_scale[k0 + acol + j], s_shift[k0 + acol + j]);
        }

        unsigned ah[2][4], al[2][4];
#pragma unroll
        for (int mt = 0; mt < 2; mt++) {
            int m = wm + mt * 16;
            uint2 A0 = As[cur][q][m + g];
            uint2 A1 = As[cur][q][m + g + 8];
            uint2 A2 = As[cur][q + 4][m + g];
            uint2 A3 = As[cur][q + 4][m + g + 8];
            ah[mt][0] = A0.x; ah[mt][1] = A1.x; ah[mt][2] = A2.x; ah[mt][3] = A3.x;
            al[mt][0] = A0.y; al[mt][1] = A1.y; al[mt][2] = A2.y; al[mt][3] = A3.y;
        }
#pragma unroll
        for (int nt = 0; nt < 4; nt++) {
            int n = wn + nt * 8 + g;
            uint2 B0 = Bs[cur][q][n];
            uint2 B1 = Bs[cur][q + 4][n];
#pragma unroll
            for (int mt = 0; mt < 2; mt++) {
                mma_bf16(c[mt][nt], ah[mt], B0.x, B1.x);
                mma_bf16(c[mt][nt], al[mt], B0.x, B1.x);
                mma_bf16(c[mt][nt], ah[mt], B0.y, B1.y);
            }
        }

        if (more) {
            As[nxt][(acol >> 1) + 0][arow] = bf16_split_pack(av[0], av[1]);
            As[nxt][(acol >> 1) + 1][arow] = bf16_split_pack(av[2], av[3]);
            asm volatile("cp.async.wait_group 0;" ::: "memory");
            __syncthreads();
        }
    }

    // phase-1 epilogue: split-pack T = relu(c + b1) into Ts[kp][row]
#pragma unroll
    for (int mt = 0; mt < 2; mt++) {
#pragma unroll
        for (int nt = 0; nt < 4; nt++) {
            int col = wn + nt * 8 + q * 2;
            float bb0 = b1[col], bb1 = b1[col + 1];
            int kp = (wn >> 1) + nt * 4 + q;
#pragma unroll
            for (int half = 0; half < 2; half++) {
                int row = wm + mt * 16 + g + half * 8;
                float v0 = fmaxf(c[mt][nt][half * 2 + 0] + bb0, 0.f);
                float v1 = fmaxf(c[mt][nt][half * 2 + 1] + bb1, 0.f);
                Ts[kp][row] = bf16_split_pack(v0, v1);
            }
        }
    }
#pragma unroll
    for (int mt = 0; mt < 2; mt++)
#pragma unroll
        for (int nt = 0; nt < 4; nt++)
#pragma unroll
            for (int j = 0; j < 4; j++) c[mt][nt][j] = 0.f;
    __syncthreads();

    // ================= phase 2: h2 = relu(T@W2 + b2) =================
    {
        uint32_t sB = (uint32_t)__cvta_generic_to_shared(&Bs[0][bkp][bnn]);
        const uint2* gB = Bw2 + (size_t)bkp * GBN + bnn;
        cp16(sB, gB); cp16(sB + 16, gB + 2);
        asm volatile("cp.async.commit_group;");
        asm volatile("cp.async.wait_group 0;" ::: "memory");
        __syncthreads();
    }

    for (int t = 0; t < 8; t++) {
        const int cur = t & 1, nxt = cur ^ 1;
        const bool more = (t + 1 < 8);
        if (more) {
            const int k0 = (t + 1) * 16;
            uint32_t sB = (uint32_t)__cvta_generic_to_shared(&Bs[nxt][bkp][bnn]);
            const uint2* gB = Bw2 + (size_t)((k0 >> 1) + bkp) * GBN + bnn;
            cp16(sB, gB); cp16(sB + 16, gB + 2);
            asm volatile("cp.async.commit_group;");
        }

        const int kpb = t * 8;
        unsigned ah[2][4], al[2][4];
#pragma unroll
        for (int mt = 0; mt < 2; mt++) {
            int m = wm + mt * 16;
            uint2 A0 = Ts[kpb + q][m + g];
            uint2 A1 = Ts[kpb + q][m + g + 8];
            uint2 A2 = Ts[kpb + q + 4][m + g];
            uint2 A3 = Ts[kpb + q + 4][m + g + 8];
            ah[mt][0] = A0.x; ah[mt][1] = A1.x; ah[mt][2] = A2.x; ah[mt][3] = A3.x;
            al[mt][0] = A0.y; al[mt][1] = A1.y; al[mt][2] = A2.y; al[mt][3] = A3.y;
        }
#pragma unroll
        for (int nt = 0; nt < 4; nt++) {
            int n = wn + nt * 8 + g;
            uint2 B0 = Bs[cur][q][n];
            uint2 B1 = Bs[cur][q + 4][n];
#pragma unroll
            for (int mt = 0; mt < 2; mt++) {
                mma_bf16(c[mt][nt], ah[mt], B0.x, B1.x);
                mma_bf16(c[mt][nt], al[mt], B0.x, B1.x);
                mma_bf16(c[mt][nt], ah[mt], B0.y, B1.y);
            }
        }

        if (more) {
            asm volatile("cp.async.wait_group 0;" ::: "memory");
            __syncthreads();
        }
    }

    // phase-2 epilogue: h2 write + bn2 stats
#pragma unroll
    for (int mt = 0; mt < 2; mt++) {
#pragma unroll
        for (int nt = 0; nt < 4; nt++) {
            int col = wn + nt * 8 + q * 2;
            float bb0 = b2[col], bb1 = b2[col + 1];
            float cs0 = 0.f, cs1 = 0.f, cq0 = 0.f, cq1 = 0.f;
#pragma unroll
            for (int half = 0; half < 2; half++) {
                int row = blockRow + wm + mt * 16 + g + half * 8;
                if (row < M) {
                    float v0 = fmaxf(c[mt][nt][half * 2 + 0] + bb0, 0.f);
                    float v1 = fmaxf(c[mt][nt][half * 2 + 1] + bb1, 0.f);
                    cs0 += v0; cs1 += v1;
                    cq0 += v0 * v0; cq1 += v1 * v1;
                    float2 o; o.x = v0; o.y = v1;
                    *(float2*)&h2[(long)row * GBN + col] = o;
                }
            }
            atomicAdd(&s_sum[col], cs0); atomicAdd(&s_sum[col + 1], cs1);
            atomicAdd(&s_sq[col], cq0);  atomicAdd(&s_sq[col + 1], cq1);
        }
    }
    __syncthreads();
    if (tid < HH) {
        atomicAdd(&stats2[tid], s_sum[tid]);
        atomicAdd(&stats2[HH + tid], s_sq[tid]);
    }
}

// ---------------- CSR build ----------------
__global__ void k_hist(const void* __restrict__ ei) {
    const int is64 = g_is64;
    long stride = (long)gridDim.x * blockDim.x;
    for (long i = (long)blockIdx.x * blockDim.x + threadIdx.x; i < EE; i += stride) {
        int dst;
        if (is64) dst = (int)((const long long*)ei)[(long)EE + i];
        else      dst = ((const int*)ei)[EE + i];
        atomicAdd(&g_rowcnt[dst], 1);
    }
}

// single-block monolithic exclusive scan over rowcnt -> rowoff/cursor
__global__ __launch_bounds__(1024) void k_scanall() {
    __shared__ int s[1024];
    const int t = threadIdx.x;
    const int base = t * 49;   // 1024*49 = 50176 >= NN
    int loc[49];
    int sum = 0;
#pragma unroll
    for (int j = 0; j < 49; j++) {
        int idx = base + j;
        int v = (idx < NN) ? g_rowcnt[idx] : 0;
        loc[j] = sum;
        sum += v;
    }
    s[t] = sum;
    __syncthreads();
    for (int d = 1; d < 1024; d <<= 1) {
        int x = (t >= d) ? s[t - d] : 0;
        __syncthreads();
        s[t] += x;
        __syncthreads();
    }
    int texcl = s[t] - sum;
#pragma unroll
    for (int j = 0; j < 49; j++) {
        int idx = base + j;
        if (idx < NN) {
            int off = texcl + loc[j];
            g_rowoff[idx] = off;
            g_cursor[idx] = off;
        }
    }
    if (t == 0) g_rowoff[NN] = s[1023];
}

__global__ void k_scatter(const void* __restrict__ ei) {
    const int is64 = g_is64;
    long stride = (long)gridDim.x * blockDim.x;
    for (long i = (long)blockIdx.x * blockDim.x + threadIdx.x; i < EE; i += stride) {
        int src, dst;
        if (is64) {
            const long long* p = (const long long*)ei;
            src = (int)p[i]; dst = (int)p[(long)EE + i];
        } else {
            const int* p = (const int*)ei;
            src = p[i]; dst = p[EE + i];
        }
        float e = g_esrc[src] + g_edst[dst];
        e = (e >= 0.f) ? e : 0.2f * e;
        int slot = atomicAdd(&g_cursor[dst], 1);
        g_csr_src[slot] = src;
        g_csr_e[slot] = e;
    }
}

// -------- fused GAT aggregation (warp/node, MLP=8 gathers) + bn0 stats --------
__global__ __launch_bounds__(256) void k_agg(const float* __restrict__ b_gat) {
    __shared__ float s_sum[HH];
    __shared__ float s_sq[HH];
    int tid = threadIdx.x;
    if (tid < HH) { s_sum[tid] = 0.f; s_sq[tid] = 0.f; }
    __syncthreads();

    int lane = tid & 31;
    int n = blockIdx.x * 8 + (tid >> 5);
    if (n < NN) {
        int beg = g_rowoff[n], end = g_rowoff[n + 1];

        float m = -3.402823466e+38f;
        for (int i = beg + lane; i < end; i += 32) m = fmaxf(m, g_csr_e[i]);
#pragma unroll
        for (int o = 16; o; o >>= 1) m = fmaxf(m, __shfl_xor_sync(0xffffffffu, m, o));

        float4 acc = make_float4(0.f, 0.f, 0.f, 0.f);
        float den = 0.f;
        for (int base = beg; base < end; base += 32) {
            int cnt = min(32, end - base);
            float ee = (base + lane < end) ? g_csr_e[base + lane] : 0.f;
            int ss = (base + lane < end) ? g_csr_src[base + lane] : 0;
            int j = 0;
            for (; j + 8 <= cnt; j += 8) {
                float e[8]; int s[8];
#pragma unroll
                for (int u = 0; u < 8; u++) {
                    e[u] = __shfl_sync(0xffffffffu, ee, j + u);
                    s[u] = __shfl_sync(0xffffffffu, ss, j + u);
                }
                float4 hv[8];
#pragma unroll
                for (int u = 0; u < 8; u++)
                    hv[u] = ((const float4*)g_h)[(long)s[u] * 32 + lane];
#pragma unroll
                for (int u = 0; u < 8; u++) {
                    float w = __expf(e[u] - m);
                    den += w;
                    acc.x = fmaf(w, hv[u].x, acc.x);
                    acc.y = fmaf(w, hv[u].y, acc.y);
                    acc.z = fmaf(w, hv[u].z, acc.z);
                    acc.w = fmaf(w, hv[u].w, acc.w);
                }
            }
            for (; j < cnt; j++) {
                float e = __shfl_sync(0xffffffffu, ee, j);
                int s = __shfl_sync(0xffffffffu, ss, j);
                float w = __expf(e - m);
                den += w;
                float4 hv = ((const float4*)g_h)[(long)s * 32 + lane];
                acc.x = fmaf(w, hv.x, acc.x);
                acc.y = fmaf(w, hv.y, acc.y);
                acc.z = fmaf(w, hv.z, acc.z);
                acc.w = fmaf(w, hv.w, acc.w);
            }
        }
        float inv = 1.f / fmaxf(den, 1e-16f);
        float4 bg = ((const float4*)b_gat)[lane];
        float4 o;
        o.x = fmaxf(fmaf(acc.x, inv, bg.x), 0.f);
        o.y = fmaxf(fmaf(acc.y, inv, bg.y), 0.f);
        o.z = fmaxf(fmaf(acc.z, inv, bg.z), 0.f);
        o.w = fmaxf(fmaf(acc.w, inv, bg.w), 0.f);
        ((float4*)g_h0)[(long)n * 32 + lane] = o;

        int c0 = lane * 4;
        atomicAdd(&s_sum[c0 + 0], o.x); atomicAdd(&s_sq[c0 + 0], o.x * o.x);
        atomicAdd(&s_sum[c0 + 1], o.y); atomicAdd(&s_sq[c0 + 1], o.y * o.y);
        atomicAdd(&s_sum[c0 + 2], o.z); atomicAdd(&s_sq[c0 + 2], o.z * o.z);
        atomicAdd(&s_sum[c0 + 3], o.w); atomicAdd(&s_sq[c0 + 3], o.w * o.w);
    }
    __syncthreads();
    if (tid < HH) {
        atomicAdd(&g_stats0[tid], s_sum[tid]);
        atomicAdd(&g_stats0[HH + tid], s_sq[tid]);
    }
}

// ---------------- final head (+inlined bn2 finalize) ----------------
__global__ void k_final(const float* __restrict__ h2,
                        const float* __restrict__ stats2,
                        const float* __restrict__ g2, const float* __restrict__ beta2,
                        const float* __restrict__ W3, const float* __restrict__ b3,
                        float* __restrict__ out) {
    __shared__ float W3s[HH * AA];
    __shared__ float b3s[AA];
    __shared__ float s_scale[HH];
    __shared__ float s_shift[HH];
    int t = threadIdx.x; // 256
    for (int i = t; i < HH * AA; i += 256) W3s[i] = W3[i];
    if (t < AA) b3s[t] = b3[t];
    if (t < HH) {
        float mu = stats2[t] / (float)NN;
        float var = stats2[HH + t] / (float)NN - mu * mu;
        float sc = g2[t] * rsqrtf(var + 1e-5f);
        s_scale[t] = sc;
        s_shift[t] = beta2[t] - mu * sc;
    }
    __syncthreads();
    int lane = t & 31;
    int n = blockIdx.x * 8 + (t >> 5);
    if (n >= NN) return;
    float hreg[4];
#pragma unroll
    for (int j = 0; j < 4; j++) {
        int c = j * 32 + lane;
        hreg[j] = fmaf(h2[(long)n * HH + c], s_scale[c], s_shift[c]);
    }
    float acc = b3s[lane];
#pragma unroll
    for (int k = 0; k < HH; k++) {
        float hv = __shfl_sync(0xffffffffu, hreg[k >> 5], k & 31);
        acc = fmaf(hv, W3s[k * AA + lane], acc);
    }
    float mx = acc;
#pragma unroll
    for (int o = 16; o; o >>= 1) mx = fmaxf(mx, __shfl_xor_sync(0xffffffffu, mx, o));
    float p = __expf(acc - mx);
    float s = p;
#pragma unroll
    for (int o = 16; o; o >>= 1) s += __shfl_xor_sync(0xffffffffu, s, o);
    out[(long)n * AA + lane] = p / s;
}

// ---------------- launch ----------------
extern "C" void kernel_launch(void* const* d_in, const int* in_sizes, int n_in,
                              void* d_out, int out_size) {
    const float* x     = (const float*)d_in[0];
    const void*  ei    = d_in[1];
    const float* W     = (const float*)d_in[2];
    const float* a_src = (const float*)d_in[3];
    const float* a_dst = (const float*)d_in[4];
    const float* b_gat = (const float*)d_in[5];
    const float* g0    = (const float*)d_in[6];
    const float* beta0 = (const float*)d_in[7];
    const float* W1    = (const float*)d_in[8];
    const float* b1    = (const float*)d_in[9];
    const float* W2    = (const float*)d_in[10];
    const float* b2    = (const float*)d_in[11];
    const float* g2    = (const float*)d_in[12];
    const float* beta2 = (const float*)d_in[13];
    const float* W3    = (const float*)d_in[14];
    const float* b3    = (const float*)d_in[15];
    float* out = (float*)d_out;

    float *p_h, *p_h0, *p_h2, *p_stats0, *p_stats2;
    uint2 *p_bw;
    cudaGetSymbolAddress((void**)&p_h, g_h);
    cudaGetSymbolAddress((void**)&p_h0, g_h0);
    cudaGetSymbolAddress((void**)&p_h2, g_h2);
    cudaGetSymbolAddress((void**)&p_stats0, g_stats0);
    cudaGetSymbolAddress((void**)&p_stats2, g_stats2);
    cudaGetSymbolAddress((void**)&p_bw, g_Bw);

    const int gemmGrid = (NN + GBM - 1) / GBM;  // 782
    const int SMEM_GEMM = (16 * ASROW + 16 * BSROW) * (int)sizeof(uint2);              // 25600
    const int SMEM_FC   = (16 * ASROW + 16 * BSROW + 64 * ASROW) * (int)sizeof(uint2); // 60416

    static cudaStream_t s1 = nullptr;
    static cudaEvent_t evFork = nullptr, evJoin = nullptr;
    if (!s1) {
        cudaFuncSetAttribute(k_fc12, cudaFuncAttributeMaxDynamicSharedMemorySize, SMEM_FC);
        cudaStreamCreateWithFlags(&s1, cudaStreamNonBlocking);
        cudaEventCreateWithFlags(&evFork, cudaEventDisableTiming);
        cudaEventCreateWithFlags(&evJoin, cudaEventDisableTiming);
    }

    // stream 0: init (detect + zero) + fused wa GEMVs
    k_init<<<196 + DIN, 256>>>((const int*)ei, W, a_src, a_dst);

    // fork: edge path on side stream (hist -> edot -> scan -> scatter)
    cudaEventRecord(evFork, 0);
    cudaStreamWaitEvent(s1, evFork, 0);
    k_hist<<<782, 256, 0, s1>>>(ei);
    k_edot<<<(NN + 7) / 8, 256, 0, s1>>>(x);
    k_scanall<<<1, 1024, 0, s1>>>();
    k_scatter<<<782, 256, 0, s1>>>(ei);
    cudaEventRecord(evJoin, s1);

    // stream 0 meanwhile: weight split + GEMM1 (h = x@W)
    k_splitW<<<128, 256>>>(W, W1, W2);
    k_gemm_bf16<<<gemmGrid, 256, SMEM_GEMM>>>(x, p_bw, p_h, NN, DIN);

    // join: agg needs CSR (s1) + g_h (stream 0)
    cudaStreamWaitEvent(0, evJoin, 0);
    k_agg<<<(NN + 7) / 8, 256>>>(b_gat);

    // fused fc1 + fc2 (inlined bn0 finalize, +bn2 stats)
    k_fc12<<<gemmGrid, 256, SMEM_FC>>>(p_h0, p_bw + OFF_W1, p_bw + OFF_W2, p_h2, NN,
                                       p_stats0, g0, beta0, b1, b2, p_stats2);

    // final head (inlined bn2 finalize)
    k_final<<<(NN + 7) / 8, 256>>>(p_h2, p_stats2, g2, beta2, W3, b3, out);
}

// round 16
// speedup vs baseline: 1.1576x; 1.1576x over previous
#include <cuda_runtime.h>
#include <cuda_bf16.h>
#include <cstdint>

#define NN 50000
#define EE 800000
#define DIN 256
#define HH 128
#define AA 32
#define NB_SCAN 196   // ceil(50000/256)

// ---------------- scratch (device globals) ----------------
__device__ float g_h   [(size_t)NN * HH];
__device__ float g_h0  [(size_t)NN * HH];
__device__ float g_h2  [(size_t)NN * HH];
__device__ float g_esrc[NN];
__device__ float g_edst[NN];
__device__ float g_wa_src[DIN];
__device__ float g_wa_dst[DIN];
__device__ int   g_rowcnt[NN];
__device__ int   g_rowoff[NN + 1];
__device__ int   g_cursor[NN];
__device__ int   g_partial[256];
__device__ int   g_csr_src[EE];
__device__ float g_csr_e[EE];
__device__ float g_stats0[2 * HH];
__device__ float g_stats2[2 * HH];
// packed bf16 hi/lo weight planes. W: kp 0..127 | W1: +16384 | W2: +24576
__device__ __align__(16) uint2 g_Bw[32768];
__device__ int   g_is64;

#define OFF_W1 16384
#define OFF_W2 24576

// ---------------- helpers ----------------
__device__ __forceinline__ uint2 bf16_split_pack(float v0, float v1) {
    __nv_bfloat16 h0 = __float2bfloat16_rn(v0);
    __nv_bfloat16 h1 = __float2bfloat16_rn(v1);
    float r0 = v0 - __bfloat162float(h0);
    float r1 = v1 - __bfloat162float(h1);
    __nv_bfloat16 l0 = __float2bfloat16_rn(r0);
    __nv_bfloat16 l1 = __float2bfloat16_rn(r1);
    uint2 w;
    w.x = (uint32_t)__bfloat16_as_ushort(h0) | ((uint32_t)__bfloat16_as_ushort(h1) << 16);
    w.y = (uint32_t)__bfloat16_as_ushort(l0) | ((uint32_t)__bfloat16_as_ushort(l1) << 16);
    return w;
}
__device__ __forceinline__ void mma_bf16(float* c, const unsigned* a, unsigned b0, unsigned b1) {
    asm volatile(
        "mma.sync.aligned.m16n8k16.row.col.f32.bf16.bf16.f32 "
        "{%0,%1,%2,%3}, {%4,%5,%6,%7}, {%8,%9}, {%0,%1,%2,%3};"
        : "+f"(c[0]), "+f"(c[1]), "+f"(c[2]), "+f"(c[3])
        : "r"(a[0]), "r"(a[1]), "r"(a[2]), "r"(a[3]), "r"(b0), "r"(b1));
}
__device__ __forceinline__ void cp16(uint32_t saddr, const void* gaddr) {
    asm volatile("cp.async.ca.shared.global [%0], [%1], 16;" :: "r"(saddr), "l"(gaddr));
}

// ---------------- init (+dtype detect) + fused W@a GEMVs ----------------
__global__ void k_init(const int* ei_words, const float* __restrict__ W,
                       const float* __restrict__ a_src, const float* __restrict__ a_dst) {
    int b = blockIdx.x;
    if (b < 196) {
        int idx = b * 256 + threadIdx.x;
        if (idx == 0) {
            int nz = 0;
            for (int i = 1; i < 2048; i += 2) nz += (ei_words[i] != 0);
            g_is64 = (nz == 0) ? 1 : 0;
        }
        if (idx < NN) g_rowcnt[idx] = 0;
        if (idx < 2 * HH) { g_stats0[idx] = 0.f; g_stats2[idx] = 0.f; }
    } else {
        __shared__ float ss[4], sd[4];
        int k = b - 196;         // 0..255
        int t = threadIdx.x;
        float s = 0.f, d = 0.f;
        if (t < 128) {
            float w = W[(size_t)k * HH + t];
            s = w * a_src[t];
            d = w * a_dst[t];
        }
#pragma unroll
        for (int o = 16; o; o >>= 1) {
            s += __shfl_xor_sync(0xffffffffu, s, o);
            d += __shfl_xor_sync(0xffffffffu, d, o);
        }
        if (t < 128 && (t & 31) == 0) { ss[t >> 5] = s; sd[t >> 5] = d; }
        __syncthreads();
        if (t == 0) g_wa_src[k] = ss[0] + ss[1] + ss[2] + ss[3];
        if (t == 1) g_wa_dst[k] = sd[0] + sd[1] + sd[2] + sd[3];
    }
}

// e_src[n] = x[n]·wa_src, e_dst[n] = x[n]·wa_dst  (warp per node)
__global__ void k_edot(const float* __restrict__ x) {
    int lane = threadIdx.x & 31;
    int n = blockIdx.x * 8 + (threadIdx.x >> 5);
    if (n >= NN) return;
    const float4* xr = (const float4*)(x + (size_t)n * DIN);
    const float4* ws = (const float4*)g_wa_src;
    const float4* wd = (const float4*)g_wa_dst;
    float4 x0 = xr[lane], x1 = xr[lane + 32];
    float4 s0 = ws[lane], s1 = ws[lane + 32];
    float4 d0 = wd[lane], d1 = wd[lane + 32];
    float s = x0.x * s0.x + x0.y * s0.y + x0.z * s0.z + x0.w * s0.w
            + x1.x * s1.x + x1.y * s1.y + x1.z * s1.z + x1.w * s1.w;
    float d = x0.x * d0.x + x0.y * d0.y + x0.z * d0.z + x0.w * d0.w
            + x1.x * d1.x + x1.y * d1.y + x1.z * d1.z + x1.w * d1.w;
#pragma unroll
    for (int o = 16; o; o >>= 1) {
        s += __shfl_xor_sync(0xffffffffu, s, o);
        d += __shfl_xor_sync(0xffffffffu, d, o);
    }
    if (lane == 0) { g_esrc[n] = s; g_edst[n] = d; }
}

// split all weights into packed bf16 hi/lo k-pair words
__global__ void k_splitW(const float* __restrict__ W, const float* __restrict__ W1,
                         const float* __restrict__ W2) {
    int i = blockIdx.x * 256 + threadIdx.x;
    if (i >= 32768) return;
    const float* src; int base;
    if (i < OFF_W1) { src = W;  base = i; }
    else if (i < OFF_W2) { src = W1; base = i - OFF_W1; }
    else { src = W2; base = i - OFF_W2; }
    int kp = base >> 7, n = base & 127;
    float v0 = src[(size_t)(2 * kp) * HH + n];
    float v1 = src[(size_t)(2 * kp + 1) * HH + n];
    g_Bw[i] = bf16_split_pack(v0, v1);
}

// ------------- 3xBF16 tensor-core GEMM, M-tile 64 (3 CTAs/SM) -------------
#define GBM 64
#define GBN 128
#define ASROW 68
#define BSROW 132

__global__ __launch_bounds__(256, 3) void k_gemm_bf16(
    const float* __restrict__ A, const uint2* __restrict__ Bw,
    float* __restrict__ C, int M, int K)
{
    extern __shared__ uint2 smem[];
    uint2 (*As)[8][ASROW] = reinterpret_cast<uint2 (*)[8][ASROW]>(smem);
    uint2 (*Bs)[8][BSROW] = reinterpret_cast<uint2 (*)[8][BSROW]>(smem + 16 * ASROW);

    const int tid = threadIdx.x;
    const int warp = tid >> 5, lane = tid & 31;
    const int g = lane >> 2, q = lane & 3;
    const int wm = (warp & 1) * 32;
    const int wn = (warp >> 1) * 32;
    const int blockRow = blockIdx.x * GBM;

    const int arow = tid >> 2;
    const int acol = (tid & 3) * 4;
    const int bkp = tid >> 5;
    const int bnn = lane * 4;

    const int aRowG = blockRow + arow;
    const bool aValid = aRowG < M;

    float c[2][4][4];
#pragma unroll
    for (int mt = 0; mt < 2; mt++)
#pragma unroll
        for (int nt = 0; nt < 4; nt++)
#pragma unroll
            for (int j = 0; j < 4; j++) c[mt][nt][j] = 0.f;

    float av[4];

    {
        uint32_t sB = (uint32_t)__cvta_generic_to_shared(&Bs[0][bkp][bnn]);
        const uint2* gB = Bw + (size_t)bkp * GBN + bnn;
        cp16(sB, gB); cp16(sB + 16, gB + 2);
        asm volatile("cp.async.commit_group;");

#pragma unroll
        for (int j = 0; j < 4; j++) av[j] = 0.f;
        if (aValid) {
            float4 v = *(const float4*)&A[(long)aRowG * K + acol];
            av[0] = v.x; av[1] = v.y; av[2] = v.z; av[3] = v.w;
        }
        As[0][(acol >> 1) + 0][arow] = bf16_split_pack(av[0], av[1]);
        As[0][(acol >> 1) + 1][arow] = bf16_split_pack(av[2], av[3]);
        asm volatile("cp.async.wait_group 0;" ::: "memory");
        __syncthreads();
    }

    const int ntiles = K / 16;
    for (int t = 0; t < ntiles; t++) {
        const int cur = t & 1, nxt = cur ^ 1;
        const bool more = (t + 1 < ntiles);
        if (more) {
            const int k0 = (t + 1) * 16;
            uint32_t sB = (uint32_t)__cvta_generic_to_shared(&Bs[nxt][bkp][bnn]);
            const uint2* gB = Bw + (size_t)((k0 >> 1) + bkp) * GBN + bnn;
            cp16(sB, gB); cp16(sB + 16, gB + 2);
            asm volatile("cp.async.commit_group;");

#pragma unroll
            for (int j = 0; j < 4; j++) av[j] = 0.f;
            if (aValid) {
                float4 v = *(const float4*)&A[(long)aRowG * K + k0 + acol];
                av[0] = v.x; av[1] = v.y; av[2] = v.z; av[3] = v.w;
            }
        }

        unsigned ah[2][4], al[2][4];
#pragma unroll
        for (int mt = 0; mt < 2; mt++) {
            int m = wm + mt * 16;
            uint2 A0 = As[cur][q][m + g];
            uint2 A1 = As[cur][q][m + g + 8];
            uint2 A2 = As[cur][q + 4][m + g];
            uint2 A3 = As[cur][q + 4][m + g + 8];
            ah[mt][0] = A0.x; ah[mt][1] = A1.x; ah[mt][2] = A2.x; ah[mt][3] = A3.x;
            al[mt][0] = A0.y; al[mt][1] = A1.y; al[mt][2] = A2.y; al[mt][3] = A3.y;
        }
#pragma unroll
        for (int nt = 0; nt < 4; nt++) {
            int n = wn + nt * 8 + g;
            uint2 B0 = Bs[cur][q][n];
            uint2 B1 = Bs[cur][q + 4][n];
#pragma unroll
            for (int mt = 0; mt < 2; mt++) {
                mma_bf16(c[mt][nt], ah[mt], B0.x, B1.x);
                mma_bf16(c[mt][nt], al[mt], B0.x, B1.x);
                mma_bf16(c[mt][nt], ah[mt], B0.y, B1.y);
            }
        }

        if (more) {
            As[nxt][(acol >> 1) + 0][arow] = bf16_split_pack(av[0], av[1]);
            As[nxt][(acol >> 1) + 1][arow] = bf16_split_pack(av[2], av[3]);
            asm volatile("cp.async.wait_group 0;" ::: "memory");
            __syncthreads();
        }
    }

#pragma unroll
    for (int mt = 0; mt < 2; mt++) {
#pragma unroll
        for (int nt = 0; nt < 4; nt++) {
            int col = wn + nt * 8 + q * 2;
#pragma unroll
            for (int half = 0; half < 2; half++) {
                int row = blockRow + wm + mt * 16 + g + half * 8;
                if (row < M) {
                    float2 o;
                    o.x = c[mt][nt][half * 2 + 0];
                    o.y = c[mt][nt][half * 2 + 1];
                    *(float2*)&C[(long)row * GBN + col] = o;
                }
            }
        }
    }
}

// ------------- fused fc1+fc2, M-tile 64 (+bn0 finalize, +bn2 stats) -------------
__global__ __launch_bounds__(256, 3) void k_fc12(
    const float* __restrict__ h0, const uint2* __restrict__ Bw1, const uint2* __restrict__ Bw2,
    float* __restrict__ h2, int M,
    const float* __restrict__ stats0,
    const float* __restrict__ g0, const float* __restrict__ beta0,
    const float* __restrict__ b1, const float* __restrict__ b2,
    float* __restrict__ stats2)
{
    extern __shared__ uint2 smem[];
    uint2 (*As)[8][ASROW] = reinterpret_cast<uint2 (*)[8][ASROW]>(smem);
    uint2 (*Bs)[8][BSROW] = reinterpret_cast<uint2 (*)[8][BSROW]>(smem + 16 * ASROW);
    uint2 (*Ts)[ASROW]    = reinterpret_cast<uint2 (*)[ASROW]>(smem + 16 * ASROW + 16 * BSROW);
    __shared__ float s_sum[HH];
    __shared__ float s_sq[HH];
    __shared__ float s_scale[HH];
    __shared__ float s_shift[HH];

    const int tid = threadIdx.x;
    const int warp = tid >> 5, lane = tid & 31;
    const int g = lane >> 2, q = lane & 3;
    const int wm = (warp & 1) * 32;
    const int wn = (warp >> 1) * 32;
    const int blockRow = blockIdx.x * GBM;

    const int arow = tid >> 2;
    const int acol = (tid & 3) * 4;
    const int bkp = tid >> 5;
    const int bnn = lane * 4;

    const int aRowG = blockRow + arow;
    const bool aValid = aRowG < M;

    if (tid < HH) {
        s_sum[tid] = 0.f; s_sq[tid] = 0.f;
        float mu = stats0[tid] / (float)NN;
        float var = stats0[HH + tid] / (float)NN - mu * mu;
        float sc = g0[tid] * rsqrtf(var + 1e-5f);
        s_scale[tid] = sc;
        s_shift[tid] = beta0[tid] - mu * sc;
    }
    __syncthreads();

    float c[2][4][4];
#pragma unroll
    for (int mt = 0; mt < 2; mt++)
#pragma unroll
        for (int nt = 0; nt < 4; nt++)
#pragma unroll
            for (int j = 0; j < 4; j++) c[mt][nt][j] = 0.f;

    float av[4];

    // ================= phase 1: T = relu(bn0(h0)@W1 + b1) =================
    {
        uint32_t sB = (uint32_t)__cvta_generic_to_shared(&Bs[0][bkp][bnn]);
        const uint2* gB = Bw1 + (size_t)bkp * GBN + bnn;
        cp16(sB, gB); cp16(sB + 16, gB + 2);
        asm volatile("cp.async.commit_group;");

#pragma unroll
        for (int j = 0; j < 4; j++) av[j] = 0.f;
        if (aValid) {
            float4 v = *(const float4*)&h0[(long)aRowG * HH + acol];
            av[0] = v.x; av[1] = v.y; av[2] = v.z; av[3] = v.w;
        }
#pragma unroll
        for (int j = 0; j < 4; j++)
            av[j] = fmaf(av[j], s_scale[acol + j], s_shift[acol + j]);
        As[0][(acol >> 1) + 0][arow] = bf16_split_pack(av[0], av[1]);
        As[0][(acol >> 1) + 1][arow] = bf16_split_pack(av[2], av[3]);
        asm volatile("cp.async.wait_group 0;" ::: "memory");
        __syncthreads();
    }

    for (int t = 0; t < 8; t++) {
        const int cur = t & 1, nxt = cur ^ 1;
        const bool more = (t + 1 < 8);
        if (more) {
            const int k0 = (t + 1) * 16;
            uint32_t sB = (uint32_t)__cvta_generic_to_shared(&Bs[nxt][bkp][bnn]);
            const uint2* gB = Bw1 + (size_t)((k0 >> 1) + bkp) * GBN + bnn;
            cp16(sB, gB); cp16(sB + 16, gB + 2);
            asm volatile("cp.async.commit_group;");

#pragma unroll
            for (int j = 0; j < 4; j++) av[j] = 0.f;
            if (aValid) {
                float4 v = *(const float4*)&h0[(long)aRowG * HH + k0 + acol];
                av[0] = v.x; av[1] = v.y; av[2] = v.z; av[3] = v.w;
            }
#pragma unroll
            for (int j = 0; j < 4; j++)
                av[j] = fmaf(av[j], s_scale[k0 + acol + j], s_shift[k0 + acol + j]);
        }

        unsigned ah[2][4], al[2][4];
#pragma unroll
        for (int mt = 0; mt < 2; mt++) {
            int m = wm + mt * 16;
            uint2 A0 = As[cur][q][m + g];
            uint2 A1 = As[cur][q][m + g + 8];
            uint2 A2 = As[cur][q + 4][m + g];
            uint2 A3 = As[cur][q + 4][m + g + 8];
            ah[mt][0] = A0.x; ah[mt][1] = A1.x; ah[mt][2] = A2.x; ah[mt][3] = A3.x;
            al[mt][0] = A0.y; al[mt][1] = A1.y; al[mt][2] = A2.y; al[mt][3] = A3.y;
        }
#pragma unroll
        for (int nt = 0; nt < 4; nt++) {
            int n = wn + nt * 8 + g;
            uint2 B0 = Bs[cur][q][n];
            uint2 B1 = Bs[cur][q + 4][n];
#pragma unroll
            for (int mt = 0; mt < 2; mt++) {
                mma_bf16(c[mt][nt], ah[mt], B0.x, B1.x);
                mma_bf16(c[mt][nt], al[mt], B0.x, B1.x);
                mma_bf16(c[mt][nt], ah[mt], B0.y, B1.y);
            }
        }

        if (more) {
            As[nxt][(acol >> 1) + 0][arow] = bf16_split_pack(av[0], av[1]);
            As[nxt][(acol >> 1) + 1][arow] = bf16_split_pack(av[2], av[3]);
            asm volatile("cp.async.wait_group 0;" ::: "memory");
            __syncthreads();
        }
    }

    // phase-1 epilogue: split-pack T = relu(c + b1) into Ts[kp][row]
#pragma unroll
    for (int mt = 0; mt < 2; mt++) {
#pragma unroll
        for (int nt = 0; nt < 4; nt++) {
            int col = wn + nt * 8 + q * 2;
            float bb0 = b1[col], bb1 = b1[col + 1];
            int kp = (wn >> 1) + nt * 4 + q;
#pragma unroll
            for (int half = 0; half < 2; half++) {
                int row = wm + mt * 16 + g + half * 8;
                float v0 = fmaxf(c[mt][nt][half * 2 + 0] + bb0, 0.f);
                float v1 = fmaxf(c[mt][nt][half * 2 + 1] + bb1, 0.f);
                Ts[kp][row] = bf16_split_pack(v0, v1);
            }
        }
    }
#pragma unroll
    for (int mt = 0; mt < 2; mt++)
#pragma unroll
        for (int nt = 0; nt < 4; nt++)
#pragma unroll
            for (int j = 0; j < 4; j++) c[mt][nt][j] = 0.f;
    __syncthreads();

    // ================= phase 2: h2 = relu(T@W2 + b2) =================
    {
        uint32_t sB = (uint32_t)__cvta_generic_to_shared(&Bs[0][bkp][bnn]);
        const uint2* gB = Bw2 + (size_t)bkp * GBN + bnn;
        cp16(sB, gB); cp16(sB + 16, gB + 2);
        asm volatile("cp.async.commit_group;");
        asm volatile("cp.async.wait_group 0;" ::: "memory");
        __syncthreads();
    }

    for (int t = 0; t < 8; t++) {
        const int cur = t & 1, nxt = cur ^ 1;
        const bool more = (t + 1 < 8);
        if (more) {
            const int k0 = (t + 1) * 16;
            uint32_t sB = (uint32_t)__cvta_generic_to_shared(&Bs[nxt][bkp][bnn]);
            const uint2* gB = Bw2 + (size_t)((k0 >> 1) + bkp) * GBN + bnn;
            cp16(sB, gB); cp16(sB + 16, gB + 2);
            asm volatile("cp.async.commit_group;");
        }

        const int kpb = t * 8;
        unsigned ah[2][4], al[2][4];
#pragma unroll
        for (int mt = 0; mt < 2; mt++) {
            int m = wm + mt * 16;
            uint2 A0 = Ts[kpb + q][m + g];
            uint2 A1 = Ts[kpb + q][m + g + 8];
            uint2 A2 = Ts[kpb + q + 4][m + g];
            uint2 A3 = Ts[kpb + q + 4][m + g + 8];
            ah[mt][0] = A0.x; ah[mt][1] = A1.x; ah[mt][2] = A2.x; ah[mt][3] = A3.x;
            al[mt][0] = A0.y; al[mt][1] = A1.y; al[mt][2] = A2.y; al[mt][3] = A3.y;
        }
#pragma unroll
        for (int nt = 0; nt < 4; nt++) {
            int n = wn + nt * 8 + g;
            uint2 B0 = Bs[cur][q][n];
            uint2 B1 = Bs[cur][q + 4][n];
#pragma unroll
            for (int mt = 0; mt < 2; mt++) {
                mma_bf16(c[mt][nt], ah[mt], B0.x, B1.x);
                mma_bf16(c[mt][nt], al[mt], B0.x, B1.x);
                mma_bf16(c[mt][nt], ah[mt], B0.y, B1.y);
            }
        }

        if (more) {
            asm volatile("cp.async.wait_group 0;" ::: "memory");
            __syncthreads();
        }
    }

    // phase-2 epilogue: h2 write + bn2 stats
#pragma unroll
    for (int mt = 0; mt < 2; mt++) {
#pragma unroll
        for (int nt = 0; nt < 4; nt++) {
            int col = wn + nt * 8 + q * 2;
            float bb0 = b2[col], bb1 = b2[col + 1];
            float cs0 = 0.f, cs1 = 0.f, cq0 = 0.f, cq1 = 0.f;
#pragma unroll
            for (int half = 0; half < 2; half++) {
                int row = blockRow + wm + mt * 16 + g + half * 8;
                if (row < M) {
                    float v0 = fmaxf(c[mt][nt][half * 2 + 0] + bb0, 0.f);
                    float v1 = fmaxf(c[mt][nt][half * 2 + 1] + bb1, 0.f);
                    cs0 += v0; cs1 += v1;
                    cq0 += v0 * v0; cq1 += v1 * v1;
                    float2 o; o.x = v0; o.y = v1;
                    *(float2*)&h2[(long)row * GBN + col] = o;
                }
            }
            atomicAdd(&s_sum[col], cs0); atomicAdd(&s_sum[col + 1], cs1);
            atomicAdd(&s_sq[col], cq0);  atomicAdd(&s_sq[col + 1], cq1);
        }
    }
    __syncthreads();
    if (tid < HH) {
        atomicAdd(&stats2[tid], s_sum[tid]);
        atomicAdd(&stats2[HH + tid], s_sq[tid]);
    }
}

// ---------------- CSR build ----------------
__global__ void k_hist(const void* __restrict__ ei) {
    const int is64 = g_is64;
    long stride = (long)gridDim.x * blockDim.x;
    for (long i = (long)blockIdx.x * blockDim.x + threadIdx.x; i < EE; i += stride) {
        int dst;
        if (is64) dst = (int)((const long long*)ei)[(long)EE + i];
        else      dst = ((const int*)ei)[EE + i];
        atomicAdd(&g_rowcnt[dst], 1);
    }
}

__global__ void k_scan1() {
    __shared__ int s[256];
    int idx = blockIdx.x * 256 + threadIdx.x;
    int v = (idx < NN) ? g_rowcnt[idx] : 0;
    s[threadIdx.x] = v;
    __syncthreads();
    for (int o = 128; o; o >>= 1) {
        if (threadIdx.x < o) s[threadIdx.x] += s[threadIdx.x + o];
        __syncthreads();
    }
    if (threadIdx.x == 0) g_partial[blockIdx.x] = s[0];
}

__global__ void k_scan2() {
    __shared__ int s[256];
    int t = threadIdx.x;
    int v = (t < NB_SCAN) ? g_partial[t] : 0;
    s[t] = v;
    __syncthreads();
#pragma unroll
    for (int d = 1; d < 256; d <<= 1) {
        int x = (t >= d) ? s[t - d] : 0;
        __syncthreads();
        s[t] += x;
        __syncthreads();
    }
    if (t < NB_SCAN) g_partial[t] = s[t] - v;
}

__global__ void k_scan3() {
    __shared__ int s[256];
    int t = threadIdx.x;
    int idx = blockIdx.x * 256 + t;
    int v = (idx < NN) ? g_rowcnt[idx] : 0;
    s[t] = v;
    __syncthreads();
#pragma unroll
    for (int d = 1; d < 256; d <<= 1) {
        int x = (t >= d) ? s[t - d] : 0;
        __syncthreads();
        s[t] += x;
        __syncthreads();
    }
    if (idx < NN) {
        int off = g_partial[blockIdx.x] + s[t] - v;
        g_rowoff[idx] = off;
        g_cursor[idx] = off;
        if (idx == NN - 1) g_rowoff[NN] = off + v;
    }
}

__global__ void k_scatter(const void* __restrict__ ei) {
    const int is64 = g_is64;
    long stride = (long)gridDim.x * blockDim.x;
    for (long i = (long)blockIdx.x * blockDim.x + threadIdx.x; i < EE; i += stride) {
        int src, dst;
        if (is64) {
            const long long* p = (const long long*)ei;
            src = (int)p[i]; dst = (int)p[(long)EE + i];
        } else {
            const int* p = (const int*)ei;
            src = p[i]; dst = p[EE + i];
        }
        float e = g_esrc[src] + g_edst[dst];
        e = (e >= 0.f) ? e : 0.2f * e;
        int slot = atomicAdd(&g_cursor[dst], 1);
        g_csr_src[slot] = src;
        g_csr_e[slot] = e;
    }
}

// -------- fused GAT aggregation (warp/node, MLP=8 gathers) + bn0 stats --------
__global__ __launch_bounds__(256) void k_agg(const float* __restrict__ b_gat) {
    __shared__ float s_sum[HH];
    __shared__ float s_sq[HH];
    int tid = threadIdx.x;
    if (tid < HH) { s_sum[tid] = 0.f; s_sq[tid] = 0.f; }
    __syncthreads();

    int lane = tid & 31;
    int n = blockIdx.x * 8 + (tid >> 5);
    if (n < NN) {
        int beg = g_rowoff[n], end = g_rowoff[n + 1];

        float m = -3.402823466e+38f;
        for (int i = beg + lane; i < end; i += 32) m = fmaxf(m, g_csr_e[i]);
#pragma unroll
        for (int o = 16; o; o >>= 1) m = fmaxf(m, __shfl_xor_sync(0xffffffffu, m, o));

        float4 acc = make_float4(0.f, 0.f, 0.f, 0.f);
        float den = 0.f;
        for (int base = beg; base < end; base += 32) {
            int cnt = min(32, end - base);
            float ee = (base + lane < end) ? g_csr_e[base + lane] : 0.f;
            int ss = (base + lane < end) ? g_csr_src[base + lane] : 0;
            int j = 0;
            for (; j + 8 <= cnt; j += 8) {
                float e[8]; int s[8];
#pragma unroll
                for (int u = 0; u < 8; u++) {
                    e[u] = __shfl_sync(0xffffffffu, ee, j + u);
                    s[u] = __shfl_sync(0xffffffffu, ss, j + u);
                }
                float4 hv[8];
#pragma unroll
                for (int u = 0; u < 8; u++)
                    hv[u] = ((const float4*)g_h)[(long)s[u] * 32 + lane];
#pragma unroll
                for (int u = 0; u < 8; u++) {
                    float w = __expf(e[u] - m);
                    den += w;
                    acc.x = fmaf(w, hv[u].x, acc.x);
                    acc.y = fmaf(w, hv[u].y, acc.y);
                    acc.z = fmaf(w, hv[u].z, acc.z);
                    acc.w = fmaf(w, hv[u].w, acc.w);
                }
            }
            for (; j < cnt; j++) {
                float e = __shfl_sync(0xffffffffu, ee, j);
                int s = __shfl_sync(0xffffffffu, ss, j);
                float w = __expf(e - m);
                den += w;
                float4 hv = ((const float4*)g_h)[(long)s * 32 + lane];
                acc.x = fmaf(w, hv.x, acc.x);
                acc.y = fmaf(w, hv.y, acc.y);
                acc.z = fmaf(w, hv.z, acc.z);
                acc.w = fmaf(w, hv.w, acc.w);
            }
        }
        float inv = 1.f / fmaxf(den, 1e-16f);
        float4 bg = ((const float4*)b_gat)[lane];
        float4 o;
        o.x = fmaxf(fmaf(acc.x, inv, bg.x), 0.f);
        o.y = fmaxf(fmaf(acc.y, inv, bg.y), 0.f);
        o.z = fmaxf(fmaf(acc.z, inv, bg.z), 0.f);
        o.w = fmaxf(fmaf(acc.w, inv, bg.w), 0.f);
        ((float4*)g_h0)[(long)n * 32 + lane] = o;

        int c0 = lane * 4;
        atomicAdd(&s_sum[c0 + 0], o.x); atomicAdd(&s_sq[c0 + 0], o.x * o.x);
        atomicAdd(&s_sum[c0 + 1], o.y); atomicAdd(&s_sq[c0 + 1], o.y * o.y);
        atomicAdd(&s_sum[c0 + 2], o.z); atomicAdd(&s_sq[c0 + 2], o.z * o.z);
        atomicAdd(&s_sum[c0 + 3], o.w); atomicAdd(&s_sq[c0 + 3], o.w * o.w);
    }
    __syncthreads();
    if (tid < HH) {
        atomicAdd(&g_stats0[tid], s_sum[tid]);
        atomicAdd(&g_stats0[HH + tid], s_sq[tid]);
    }
}

// ---------------- final head (+inlined bn2 finalize) ----------------
__global__ void k_final(const float* __restrict__ h2,
                        const float* __restrict__ stats2,
                        const float* __restrict__ g2, const float* __restrict__ beta2,
                        const float* __restrict__ W3, const float* __restrict__ b3,
                        float* __restrict__ out) {
    __shared__ float W3s[HH * AA];
    __shared__ float b3s[AA];
    __shared__ float s_scale[HH];
    __shared__ float s_shift[HH];
    int t = threadIdx.x; // 256
    for (int i = t; i < HH * AA; i += 256) W3s[i] = W3[i];
    if (t < AA) b3s[t] = b3[t];
    if (t < HH) {
        float mu = stats2[t] / (float)NN;
        float var = stats2[HH + t] / (float)NN - mu * mu;
        float sc = g2[t] * rsqrtf(var + 1e-5f);
        s_scale[t] = sc;
        s_shift[t] = beta2[t] - mu * sc;
    }
    __syncthreads();
    int lane = t & 31;
    int n = blockIdx.x * 8 + (t >> 5);
    if (n >= NN) return;
    float hreg[4];
#pragma unroll
    for (int j = 0; j < 4; j++) {
        int c = j * 32 + lane;
        hreg[j] = fmaf(h2[(long)n * HH + c], s_scale[c], s_shift[c]);
    }
    float acc = b3s[lane];
#pragma unroll
    for (int k = 0; k < HH; k++) {
        float hv = __shfl_sync(0xffffffffu, hreg[k >> 5], k & 31);
        acc = fmaf(hv, W3s[k * AA + lane], acc);
    }
    float mx = acc;
#pragma unroll
    for (int o = 16; o; o >>= 1) mx = fmaxf(mx, __shfl_xor_sync(0xffffffffu, mx, o));
    float p = __expf(acc - mx);
    float s = p;
#pragma unroll
    for (int o = 16; o; o >>= 1) s += __shfl_xor_sync(0xffffffffu, s, o);
    out[(long)n * AA + lane] = p / s;
}

// ---------------- launch ----------------
extern "C" void kernel_launch(void* const* d_in, const int* in_sizes, int n_in,
                              void* d_out, int out_size) {
    const float* x     = (const float*)d_in[0];
    const void*  ei    = d_in[1];
    const float* W     = (const float*)d_in[2];
    const float* a_src = (const float*)d_in[3];
    const float* a_dst = (const float*)d_in[4];
    const float* b_gat = (const float*)d_in[5];
    const float* g0    = (const float*)d_in[6];
    const float* beta0 = (const float*)d_in[7];
    const float* W1    = (const float*)d_in[8];
    const float* b1    = (const float*)d_in[9];
    const float* W2    = (const float*)d_in[10];
    const float* b2    = (const float*)d_in[11];
    const float* g2    = (const float*)d_in[12];
    const float* beta2 = (const float*)d_in[13];
    const float* W3    = (const float*)d_in[14];
    const float* b3    = (const float*)d_in[15];
    float* out = (float*)d_out;

    float *p_h, *p_h0, *p_h2, *p_stats0, *p_stats2;
    uint2 *p_bw;
    cudaGetSymbolAddress((void**)&p_h, g_h);
    cudaGetSymbolAddress((void**)&p_h0, g_h0);
    cudaGetSymbolAddress((void**)&p_h2, g_h2);
    cudaGetSymbolAddress((void**)&p_stats0, g_stats0);
    cudaGetSymbolAddress((void**)&p_stats2, g_stats2);
    cudaGetSymbolAddress((void**)&p_bw, g_Bw);

    const int gemmGrid = (NN + GBM - 1) / GBM;  // 782
    const int SMEM_GEMM = (16 * ASROW + 16 * BSROW) * (int)sizeof(uint2);              // 25600
    const int SMEM_FC   = (16 * ASROW + 16 * BSROW + 64 * ASROW) * (int)sizeof(uint2); // 60416

    static cudaStream_t s1 = nullptr;
    static cudaEvent_t evFork = nullptr, evJoin = nullptr;
    if (!s1) {
        cudaFuncSetAttribute(k_fc12, cudaFuncAttributeMaxDynamicSharedMemorySize, SMEM_FC);
        cudaStreamCreateWithFlags(&s1, cudaStreamNonBlocking);
        cudaEventCreateWithFlags(&evFork, cudaEventDisableTiming);
        cudaEventCreateWithFlags(&evJoin, cudaEventDisableTiming);
    }

    // stream 0: init (detect + zero) + fused wa GEMVs
    k_init<<<196 + DIN, 256>>>((const int*)ei, W, a_src, a_dst);

    // fork: edge path on side stream (hist -> edot -> scans -> scatter)
    cudaEventRecord(evFork, 0);
    cudaStreamWaitEvent(s1, evFork, 0);
    k_hist<<<782, 256, 0, s1>>>(ei);
    k_edot<<<(NN + 7) / 8, 256, 0, s1>>>(x);
    k_scan1<<<NB_SCAN, 256, 0, s1>>>();
    k_scan2<<<1, 256, 0, s1>>>();
    k_scan3<<<NB_SCAN, 256, 0, s1>>>();
    k_scatter<<<782, 256, 0, s1>>>(ei);
    cudaEventRecord(evJoin, s1);

    // stream 0 meanwhile: weight split + GEMM1 (h = x@W)
    k_splitW<<<128, 256>>>(W, W1, W2);
    k_gemm_bf16<<<gemmGrid, 256, SMEM_GEMM>>>(x, p_bw, p_h, NN, DIN);

    // join: agg needs CSR (s1) + g_h (stream 0)
    cudaStreamWaitEvent(0, evJoin, 0);
    k_agg<<<(NN + 7) / 8, 256>>>(b_gat);

    // fused fc1 + fc2 (inlined bn0 finalize, +bn2 stats)
    k_fc12<<<gemmGrid, 256, SMEM_FC>>>(p_h0, p_bw + OFF_W1, p_bw + OFF_W2, p_h2, NN,
                                       p_stats0, g0, beta0, b1, b2, p_stats2);

    // final head (inlined bn2 finalize)
    k_final<<<(NN + 7) / 8, 256>>>(p_h2, p_stats2, g2, beta2, W3, b3, out);
}

// round 17
// speedup vs baseline: 1.1802x; 1.0195x over previous
#include <cuda_runtime.h>
#include <cuda_bf16.h>
#include <cstdint>

#define NN 50000
#define EE 800000
#define DIN 256
#define HH 128
#define AA 32
#define NB_SCAN 196   // ceil(50000/256)

// ---------------- scratch (device globals; zero-initialized at load) ----------------
__device__ float g_h   [(size_t)NN * HH];
__device__ float g_h0  [(size_t)NN * HH];
__device__ float g_h2  [(size_t)NN * HH];
__device__ float g_esrc[NN];
__device__ float g_edst[NN];
__device__ float g_wa_src[DIN];
__device__ float g_wa_dst[DIN];
__device__ int   g_rowcnt[NN];          // zeroed by k_scatter each iteration
__device__ int   g_rowoff[NN + 1];
__device__ int   g_cursor[NN];
__device__ int   g_partial[256];
__device__ int   g_csr_src[EE];
__device__ float g_csr_e[EE];
__device__ float g_stats0[2 * HH];      // zeroed by k_scatter each iteration
__device__ float g_stats2[2 * HH];      // zeroed by k_scatter each iteration
// packed bf16 hi/lo weight planes. W: kp 0..127 | W1: +16384 | W2: +24576
__device__ __align__(16) uint2 g_Bw[32768];
__device__ int   g_is64;

#define OFF_W1 16384
#define OFF_W2 24576

// ---------------- helpers ----------------
__device__ __forceinline__ void load_edge(const void* ei, long i, int& src, int& dst) {
    if (g_is64) {
        const long long* p = (const long long*)ei;
        src = (int)p[i]; dst = (int)p[(long)EE + i];
    } else {
        const int* p = (const int*)ei;
        src = p[i]; dst = p[EE + i];
    }
}
__device__ __forceinline__ uint2 bf16_split_pack(float v0, float v1) {
    __nv_bfloat16 h0 = __float2bfloat16_rn(v0);
    __nv_bfloat16 h1 = __float2bfloat16_rn(v1);
    float r0 = v0 - __bfloat162float(h0);
    float r1 = v1 - __bfloat162float(h1);
    __nv_bfloat16 l0 = __float2bfloat16_rn(r0);
    __nv_bfloat16 l1 = __float2bfloat16_rn(r1);
    uint2 w;
    w.x = (uint32_t)__bfloat16_as_ushort(h0) | ((uint32_t)__bfloat16_as_ushort(h1) << 16);
    w.y = (uint32_t)__bfloat16_as_ushort(l0) | ((uint32_t)__bfloat16_as_ushort(l1) << 16);
    return w;
}
__device__ __forceinline__ void mma_bf16(float* c, const unsigned* a, unsigned b0, unsigned b1) {
    asm volatile(
        "mma.sync.aligned.m16n8k16.row.col.f32.bf16.bf16.f32 "
        "{%0,%1,%2,%3}, {%4,%5,%6,%7}, {%8,%9}, {%0,%1,%2,%3};"
        : "+f"(c[0]), "+f"(c[1]), "+f"(c[2]), "+f"(c[3])
        : "r"(a[0]), "r"(a[1]), "r"(a[2]), "r"(a[3]), "r"(b0), "r"(b1));
}
__device__ __forceinline__ void cp16(uint32_t saddr, const void* gaddr) {
    asm volatile("cp.async.ca.shared.global [%0], [%1], 16;" :: "r"(saddr), "l"(gaddr));
}

// ---------------- dtype detect only ----------------
__global__ void k_detect(const int* ei_words) {
    if (threadIdx.x == 0) {
        int nz = 0;
        for (int i = 1; i < 2048; i += 2) nz += (ei_words[i] != 0);
        g_is64 = (nz == 0) ? 1 : 0;
    }
}

// wa_src = W @ a_src, wa_dst = W @ a_dst  (block per k-row)
__global__ void k_wa(const float* __restrict__ W, const float* __restrict__ a_src,
                     const float* __restrict__ a_dst) {
    __shared__ float ss[4], sd[4];
    int k = blockIdx.x;
    int t = threadIdx.x;     // 128
    float w = W[(size_t)k * HH + t];
    float s = w * a_src[t];
    float d = w * a_dst[t];
#pragma unroll
    for (int o = 16; o; o >>= 1) {
        s += __shfl_xor_sync(0xffffffffu, s, o);
        d += __shfl_xor_sync(0xffffffffu, d, o);
    }
    if ((t & 31) == 0) { ss[t >> 5] = s; sd[t >> 5] = d; }
    __syncthreads();
    if (t == 0) g_wa_src[k] = ss[0] + ss[1] + ss[2] + ss[3];
    if (t == 1) g_wa_dst[k] = sd[0] + sd[1] + sd[2] + sd[3];
}

// e_src[n] = x[n]·wa_src, e_dst[n] = x[n]·wa_dst  (warp per node)
__global__ void k_edot(const float* __restrict__ x) {
    int lane = threadIdx.x & 31;
    int n = blockIdx.x * 8 + (threadIdx.x >> 5);
    if (n >= NN) return;
    const float4* xr = (const float4*)(x + (size_t)n * DIN);
    const float4* ws = (const float4*)g_wa_src;
    const float4* wd = (const float4*)g_wa_dst;
    float4 x0 = xr[lane], x1 = xr[lane + 32];
    float4 s0 = ws[lane], s1 = ws[lane + 32];
    float4 d0 = wd[lane], d1 = wd[lane + 32];
    float s = x0.x * s0.x + x0.y * s0.y + x0.z * s0.z + x0.w * s0.w
            + x1.x * s1.x + x1.y * s1.y + x1.z * s1.z + x1.w * s1.w;
    float d = x0.x * d0.x + x0.y * d0.y + x0.z * d0.z + x0.w * d0.w
            + x1.x * d1.x + x1.y * d1.y + x1.z * d1.z + x1.w * d1.w;
#pragma unroll
    for (int o = 16; o; o >>= 1) {
        s += __shfl_xor_sync(0xffffffffu, s, o);
        d += __shfl_xor_sync(0xffffffffu, d, o);
    }
    if (lane == 0) { g_esrc[n] = s; g_edst[n] = d; }
}

// split W (k-pair words 0..16383) — needed before GEMM1 (main stream)
__global__ void k_splitW0(const float* __restrict__ W) {
    int i = blockIdx.x * 256 + threadIdx.x;
    if (i >= OFF_W1) return;
    int kp = i >> 7, n = i & 127;
    g_Bw[i] = bf16_split_pack(W[(size_t)(2 * kp) * HH + n], W[(size_t)(2 * kp + 1) * HH + n]);
}
// split W1+W2 — needed before fc12 (side stream). 8192 words/matrix = 64 kp x 128 n.
__global__ void k_splitW12(const float* __restrict__ W1, const float* __restrict__ W2) {
    int i = blockIdx.x * 256 + threadIdx.x;
    if (i >= 16384) return;
    const float* src = (i < 8192) ? W1 : W2;
    int base = (i < 8192) ? i : i - 8192;
    int kp = base >> 7, n = base & 127;
    g_Bw[OFF_W1 + i] = bf16_split_pack(src[(size_t)(2 * kp) * HH + n],
                                       src[(size_t)(2 * kp + 1) * HH + n]);
}

// ------------- 3xBF16 tensor-core GEMM, M-tile 64 (3 CTAs/SM) -------------
#define GBM 64
#define GBN 128
#define ASROW 68
#define BSROW 132

__global__ __launch_bounds__(256, 3) void k_gemm_bf16(
    const float* __restrict__ A, const uint2* __restrict__ Bw,
    float* __restrict__ C, int M, int K)
{
    extern __shared__ uint2 smem[];
    uint2 (*As)[8][ASROW] = reinterpret_cast<uint2 (*)[8][ASROW]>(smem);
    uint2 (*Bs)[8][BSROW] = reinterpret_cast<uint2 (*)[8][BSROW]>(smem + 16 * ASROW);

    const int tid = threadIdx.x;
    const int warp = tid >> 5, lane = tid & 31;
    const int g = lane >> 2, q = lane & 3;
    const int wm = (warp & 1) * 32;
    const int wn = (warp >> 1) * 32;
    const int blockRow = blockIdx.x * GBM;

    const int arow = tid >> 2;
    const int acol = (tid & 3) * 4;
    const int bkp = tid >> 5;
    const int bnn = lane * 4;

    const int aRowG = blockRow + arow;
    const bool aValid = aRowG < M;

    float c[2][4][4];
#pragma unroll
    for (int mt = 0; mt < 2; mt++)
#pragma unroll
        for (int nt = 0; nt < 4; nt++)
#pragma unroll
            for (int j = 0; j < 4; j++) c[mt][nt][j] = 0.f;

    float av[4];

    {
        uint32_t sB = (uint32_t)__cvta_generic_to_shared(&Bs[0][bkp][bnn]);
        const uint2* gB = Bw + (size_t)bkp * GBN + bnn;
        cp16(sB, gB); cp16(sB + 16, gB + 2);
        asm volatile("cp.async.commit_group;");

#pragma unroll
        for (int j = 0; j < 4; j++) av[j] = 0.f;
        if (aValid) {
            float4 v = *(const float4*)&A[(long)aRowG * K + acol];
            av[0] = v.x; av[1] = v.y; av[2] = v.z; av[3] = v.w;
        }
        As[0][(acol >> 1) + 0][arow] = bf16_split_pack(av[0], av[1]);
        As[0][(acol >> 1) + 1][arow] = bf16_split_pack(av[2], av[3]);
        asm volatile("cp.async.wait_group 0;" ::: "memory");
        __syncthreads();
    }

    const int ntiles = K / 16;
    for (int t = 0; t < ntiles; t++) {
        const int cur = t & 1, nxt = cur ^ 1;
        const bool more = (t + 1 < ntiles);
        if (more) {
            const int k0 = (t + 1) * 16;
            uint32_t sB = (uint32_t)__cvta_generic_to_shared(&Bs[nxt][bkp][bnn]);
            const uint2* gB = Bw + (size_t)((k0 >> 1) + bkp) * GBN + bnn;
            cp16(sB, gB); cp16(sB + 16, gB + 2);
            asm volatile("cp.async.commit_group;");

#pragma unroll
            for (int j = 0; j < 4; j++) av[j] = 0.f;
            if (aValid) {
                float4 v = *(const float4*)&A[(long)aRowG * K + k0 + acol];
                av[0] = v.x; av[1] = v.y; av[2] = v.z; av[3] = v.w;
            }
        }

        unsigned ah[2][4], al[2][4];
#pragma unroll
        for (int mt = 0; mt < 2; mt++) {
            int m = wm + mt * 16;
            uint2 A0 = As[cur][q][m + g];
            uint2 A1 = As[cur][q][m + g + 8];
            uint2 A2 = As[cur][q + 4][m + g];
            uint2 A3 = As[cur][q + 4][m + g + 8];
            ah[mt][0] = A0.x; ah[mt][1] = A1.x; ah[mt][2] = A2.x; ah[mt][3] = A3.x;
            al[mt][0] = A0.y; al[mt][1] = A1.y; al[mt][2] = A2.y; al[mt][3] = A3.y;
        }
#pragma unroll
        for (int nt = 0; nt < 4; nt++) {
            int n = wn + nt * 8 + g;
            uint2 B0 = Bs[cur][q][n];
            uint2 B1 = Bs[cur][q + 4][n];
#pragma unroll
            for (int mt = 0; mt < 2; mt++) {
                mma_bf16(c[mt][nt], ah[mt], B0.x, B1.x);
                mma_bf16(c[mt][nt], al[mt], B0.x, B1.x);
                mma_bf16(c[mt][nt], ah[mt], B0.y, B1.y);
            }
        }

        if (more) {
            As[nxt][(acol >> 1) + 0][arow] = bf16_split_pack(av[0], av[1]);
            As[nxt][(acol >> 1) + 1][arow] = bf16_split_pack(av[2], av[3]);
            asm volatile("cp.async.wait_group 0;" ::: "memory");
            __syncthreads();
        }
    }

#pragma unroll
    for (int mt = 0; mt < 2; mt++) {
#pragma unroll
        for (int nt = 0; nt < 4; nt++) {
            int col = wn + nt * 8 + q * 2;
#pragma unroll
            for (int half = 0; half < 2; half++) {
                int row = blockRow + wm + mt * 16 + g + half * 8;
                if (row < M) {
                    float2 o;
                    o.x = c[mt][nt][half * 2 + 0];
                    o.y = c[mt][nt][half * 2 + 1];
                    *(float2*)&C[(long)row * GBN + col] = o;
                }
            }
        }
    }
}

// ------------- fused fc1+fc2, M-tile 64 (+bn0 finalize, +bn2 stats) -------------
__global__ __launch_bounds__(256, 3) void k_fc12(
    const float* __restrict__ h0, const uint2* __restrict__ Bw1, const uint2* __restrict__ Bw2,
    float* __restrict__ h2, int M,
    const float* __restrict__ stats0,
    const float* __restrict__ g0, const float* __restrict__ beta0,
    const float* __restrict__ b1, const float* __restrict__ b2,
    float* __restrict__ stats2)
{
    extern __shared__ uint2 smem[];
    uint2 (*As)[8][ASROW] = reinterpret_cast<uint2 (*)[8][ASROW]>(smem);
    uint2 (*Bs)[8][BSROW] = reinterpret_cast<uint2 (*)[8][BSROW]>(smem + 16 * ASROW);
    uint2 (*Ts)[ASROW]    = reinterpret_cast<uint2 (*)[ASROW]>(smem + 16 * ASROW + 16 * BSROW);
    __shared__ float s_sum[HH];
    __shared__ float s_sq[HH];
    __shared__ float s_scale[HH];
    __shared__ float s_shift[HH];

    const int tid = threadIdx.x;
    const int warp = tid >> 5, lane = tid & 31;
    const int g = lane >> 2, q = lane & 3;
    const int wm = (warp & 1) * 32;
    const int wn = (warp >> 1) * 32;
    const int blockRow = blockIdx.x * GBM;

    const int arow = tid >> 2;
    const int acol = (tid & 3) * 4;
    const int bkp = tid >> 5;
    const int bnn = lane * 4;

    const int aRowG = blockRow + arow;
    const bool aValid = aRowG < M;

    if (tid < HH) {
        s_sum[tid] = 0.f; s_sq[tid] = 0.f;
        float mu = stats0[tid] / (float)NN;
        float var = stats0[HH + tid] / (float)NN - mu * mu;
        float sc = g0[tid] * rsqrtf(var + 1e-5f);
        s_scale[tid] = sc;
        s_shift[tid] = beta0[tid] - mu * sc;
    }
    __syncthreads();

    float c[2][4][4];
#pragma unroll
    for (int mt = 0; mt < 2; mt++)
#pragma unroll
        for (int nt = 0; nt < 4; nt++)
#pragma unroll
            for (int j = 0; j < 4; j++) c[mt][nt][j] = 0.f;

    float av[4];

    // ================= phase 1: T = relu(bn0(h0)@W1 + b1) =================
    {
        uint32_t sB = (uint32_t)__cvta_generic_to_shared(&Bs[0][bkp][bnn]);
        const uint2* gB = Bw1 + (size_t)bkp * GBN + bnn;
        cp16(sB, gB); cp16(sB + 16, gB + 2);
        asm volatile("cp.async.commit_group;");

#pragma unroll
        for (int j = 0; j < 4; j++) av[j] = 0.f;
        if (aValid) {
            float4 v = *(const float4*)&h0[(long)aRowG * HH + acol];
            av[0] = v.x; av[1] = v.y; av[2] = v.z; av[3] = v.w;
        }
#pragma unroll
        for (int j = 0; j < 4; j++)
            av[j] = fmaf(av[j], s_scale[acol + j], s_shift[acol + j]);
        As[0][(acol >> 1) + 0][arow] = bf16_split_pack(av[0], av[1]);
        As[0][(acol >> 1) + 1][arow] = bf16_split_pack(av[2], av[3]);
        asm volatile("cp.async.wait_group 0;" ::: "memory");
        __syncthreads();
    }

    for (int t = 0; t < 8; t++) {
        const int cur = t & 1, nxt = cur ^ 1;
        const bool more = (t + 1 < 8);
        if (more) {
            const int k0 = (t + 1) * 16;
            uint32_t sB = (uint32_t)__cvta_generic_to_shared(&Bs[nxt][bkp][bnn]);
            const uint2* gB = Bw1 + (size_t)((k0 >> 1) + bkp) * GBN + bnn;
            cp16(sB, gB); cp16(sB + 16, gB + 2);
            asm volatile("cp.async.commit_group;");

#pragma unroll
            for (int j = 0; j < 4; j++) av[j] = 0.f;
            if (aValid) {
                float4 v = *(const float4*)&h0[(long)aRowG * HH + k0 + acol];
                av[0] = v.x; av[1] = v.y; av[2] = v.z; av[3] = v.w;
            }
#pragma unroll
            for (int j = 0; j < 4; j++)
                av[j] = fmaf(av[j], s_scale[k0 + acol + j], s_shift[k0 + acol + j]);
        }

        unsigned ah[2][4], al[2][4];
#pragma unroll
        for (int mt = 0; mt < 2; mt++) {
            int m = wm + mt * 16;
            uint2 A0 = As[cur][q][m + g];
            uint2 A1 = As[cur][q][m + g + 8];
            uint2 A2 = As[cur][q + 4][m + g];
            uint2 A3 = As[cur][q + 4][m + g + 8];
            ah[mt][0] = A0.x; ah[mt][1] = A1.x; ah[mt][2] = A2.x; ah[mt][3] = A3.x;
            al[mt][0] = A0.y; al[mt][1] = A1.y; al[mt][2] = A2.y; al[mt][3] = A3.y;
        }
#pragma unroll
        for (int nt = 0; nt < 4; nt++) {
            int n = wn + nt * 8 + g;
            uint2 B0 = Bs[cur][q][n];
            uint2 B1 = Bs[cur][q + 4][n];
#pragma unroll
            for (int mt = 0; mt < 2; mt++) {
                mma_bf16(c[mt][nt], ah[mt], B0.x, B1.x);
                mma_bf16(c[mt][nt], al[mt], B0.x, B1.x);
                mma_bf16(c[mt][nt], ah[mt], B0.y, B1.y);
            }
        }

        if (more) {
            As[nxt][(acol >> 1) + 0][arow] = bf16_split_pack(av[0], av[1]);
            As[nxt][(acol >> 1) + 1][arow] = bf16_split_pack(av[2], av[3]);
            asm volatile("cp.async.wait_group 0;" ::: "memory");
            __syncthreads();
        }
    }

    // phase-1 epilogue: split-pack T = relu(c + b1) into Ts[kp][row]
#pragma unroll
    for (int mt = 0; mt < 2; mt++) {
#pragma unroll
        for (int nt = 0; nt < 4; nt++) {
            int col = wn + nt * 8 + q * 2;
            float bb0 = b1[col], bb1 = b1[col + 1];
            int kp = (wn >> 1) + nt * 4 + q;
#pragma unroll
            for (int half = 0; half < 2; half++) {
                int row = wm + mt * 16 + g + half * 8;
                float v0 = fmaxf(c[mt][nt][half * 2 + 0] + bb0, 0.f);
                float v1 = fmaxf(c[mt][nt][half * 2 + 1] + bb1, 0.f);
                Ts[kp][row] = bf16_split_pack(v0, v1);
            }
        }
    }
#pragma unroll
    for (int mt = 0; mt < 2; mt++)
#pragma unroll
        for (int nt = 0; nt < 4; nt++)
#pragma unroll
            for (int j = 0; j < 4; j++) c[mt][nt][j] = 0.f;
    __syncthreads();

    // ================= phase 2: h2 = relu(T@W2 + b2) =================
    {
        uint32_t sB = (uint32_t)__cvta_generic_to_shared(&Bs[0][bkp][bnn]);
        const uint2* gB = Bw2 + (size_t)bkp * GBN + bnn;
        cp16(sB, gB); cp16(sB + 16, gB + 2);
        asm volatile("cp.async.commit_group;");
        asm volatile("cp.async.wait_group 0;" ::: "memory");
        __syncthreads();
    }

    for (int t = 0; t < 8; t++) {
        const int cur = t & 1, nxt = cur ^ 1;
        const bool more = (t + 1 < 8);
        if (more) {
            const int k0 = (t + 1) * 16;
            uint32_t sB = (uint32_t)__cvta_generic_to_shared(&Bs[nxt][bkp][bnn]);
            const uint2* gB = Bw2 + (size_t)((k0 >> 1) + bkp) * GBN + bnn;
            cp16(sB, gB); cp16(sB + 16, gB + 2);
            asm volatile("cp.async.commit_group;");
        }

        const int kpb = t * 8;
        unsigned ah[2][4], al[2][4];
#pragma unroll
        for (int mt = 0; mt < 2; mt++) {
            int m = wm + mt * 16;
            uint2 A0 = Ts[kpb + q][m + g];
            uint2 A1 = Ts[kpb + q][m + g + 8];
            uint2 A2 = Ts[kpb + q + 4][m + g];
            uint2 A3 = Ts[kpb + q + 4][m + g + 8];
            ah[mt][0] = A0.x; ah[mt][1] = A1.x; ah[mt][2] = A2.x; ah[mt][3] = A3.x;
            al[mt][0] = A0.y; al[mt][1] = A1.y; al[mt][2] = A2.y; al[mt][3] = A3.y;
        }
#pragma unroll
        for (int nt = 0; nt < 4; nt++) {
            int n = wn + nt * 8 + g;
            uint2 B0 = Bs[cur][q][n];
            uint2 B1 = Bs[cur][q + 4][n];
#pragma unroll
            for (int mt = 0; mt < 2; mt++) {
                mma_bf16(c[mt][nt], ah[mt], B0.x, B1.x);
                mma_bf16(c[mt][nt], al[mt], B0.x, B1.x);
                mma_bf16(c[mt][nt], ah[mt], B0.y, B1.y);
            }
        }

        if (more) {
            asm volatile("cp.async.wait_group 0;" ::: "memory");
            __syncthreads();
        }
    }

    // phase-2 epilogue: h2 write + bn2 stats
#pragma unroll
    for (int mt = 0; mt < 2; mt++) {
#pragma unroll
        for (int nt = 0; nt < 4; nt++) {
            int col = wn + nt * 8 + q * 2;
            float bb0 = b2[col], bb1 = b2[col + 1];
            float cs0 = 0.f, cs1 = 0.f, cq0 = 0.f, cq1 = 0.f;
#pragma unroll
            for (int half = 0; half < 2; half++) {
                int row = blockRow + wm + mt * 16 + g + half * 8;
                if (row < M) {
                    float v0 = fmaxf(c[mt][nt][half * 2 + 0] + bb0, 0.f);
                    float v1 = fmaxf(c[mt][nt][half * 2 + 1] + bb1, 0.f);
                    cs0 += v0; cs1 += v1;
                    cq0 += v0 * v0; cq1 += v1 * v1;
                    float2 o; o.x = v0; o.y = v1;
                    *(float2*)&h2[(long)row * GBN + col] = o;
                }
            }
            atomicAdd(&s_sum[col], cs0); atomicAdd(&s_sum[col + 1], cs1);
            atomicAdd(&s_sq[col], cq0);  atomicAdd(&s_sq[col + 1], cq1);
        }
    }
    __syncthreads();
    if (tid < HH) {
        atomicAdd(&stats2[tid], s_sum[tid]);
        atomicAdd(&stats2[HH + tid], s_sq[tid]);
    }
}

// ---------------- CSR build ----------------
__global__ void k_hist(const void* __restrict__ ei) {
    long i = (long)blockIdx.x * blockDim.x + threadIdx.x;
    if (i >= EE) return;
    int dst;
    if (g_is64) dst = (int)((const long long*)ei)[(long)EE + i];
    else        dst = ((const int*)ei)[EE + i];
    atomicAdd(&g_rowcnt[dst], 1);
}

__global__ void k_scan1() {
    __shared__ int s[256];
    int idx = blockIdx.x * 256 + threadIdx.x;
    int v = (idx < NN) ? g_rowcnt[idx] : 0;
    s[threadIdx.x] = v;
    __syncthreads();
    for (int o = 128; o; o >>= 1) {
        if (threadIdx.x < o) s[threadIdx.x] += s[threadIdx.x + o];
        __syncthreads();
    }
    if (threadIdx.x == 0) g_partial[blockIdx.x] = s[0];
}

__global__ void k_scan2() {
    __shared__ int s[256];
    int t = threadIdx.x;
    int v = (t < NB_SCAN) ? g_partial[t] : 0;
    s[t] = v;
    __syncthreads();
#pragma unroll
    for (int d = 1; d < 256; d <<= 1) {
        int x = (t >= d) ? s[t - d] : 0;
        __syncthreads();
        s[t] += x;
        __syncthreads();
    }
    if (t < NB_SCAN) g_partial[t] = s[t] - v;
}

__global__ void k_scan3() {
    __shared__ int s[256];
    int t = threadIdx.x;
    int idx = blockIdx.x * 256 + t;
    int v = (idx < NN) ? g_rowcnt[idx] : 0;
    s[t] = v;
    __syncthreads();
#pragma unroll
    for (int d = 1; d < 256; d <<= 1) {
        int x = (t >= d) ? s[t - d] : 0;
        __syncthreads();
        s[t] += x;
        __syncthreads();
    }
    if (idx < NN) {
        int off = g_partial[blockIdx.x] + s[t] - v;
        g_rowoff[idx] = off;
        g_cursor[idx] = off;
        if (idx == NN - 1) g_rowoff[NN] = off + v;
    }
}

// scatter + deferred zeroing of rowcnt/stats for the NEXT iteration
__global__ void k_scatter(const void* __restrict__ ei) {
    long i = (long)blockIdx.x * blockDim.x + threadIdx.x;
    if (i < NN) g_rowcnt[i] = 0;                      // consumed by scan3 already
    if (i < 2 * HH) { g_stats0[i] = 0.f; g_stats2[i] = 0.f; }  // accumulated later by agg/fc12
    if (i >= EE) return;
    int src, dst;
    load_edge(ei, i, src, dst);
    float e = g_esrc[src] + g_edst[dst];
    e = (e >= 0.f) ? e : 0.2f * e;
    int slot = atomicAdd(&g_cursor[dst], 1);
    g_csr_src[slot] = src;
    g_csr_e[slot] = e;
}

// -------- fused GAT aggregation (warp/node, MLP=8 gathers) + bn0 stats --------
__global__ __launch_bounds__(256) void k_agg(const float* __restrict__ b_gat) {
    __shared__ float s_sum[HH];
    __shared__ float s_sq[HH];
    int tid = threadIdx.x;
    if (tid < HH) { s_sum[tid] = 0.f; s_sq[tid] = 0.f; }
    __syncthreads();

    int lane = tid & 31;
    int n = blockIdx.x * 8 + (tid >> 5);
    if (n < NN) {
        int beg = g_rowoff[n], end = g_rowoff[n + 1];

        float m = -3.402823466e+38f;
        for (int i = beg + lane; i < end; i += 32) m = fmaxf(m, g_csr_e[i]);
#pragma unroll
        for (int o = 16; o; o >>= 1) m = fmaxf(m, __shfl_xor_sync(0xffffffffu, m, o));

        float4 acc = make_float4(0.f, 0.f, 0.f, 0.f);
        float den = 0.f;
        for (int base = beg; base < end; base += 32) {
            int cnt = min(32, end - base);
            float ee = (base + lane < end) ? g_csr_e[base + lane] : 0.f;
            int ss = (base + lane < end) ? g_csr_src[base + lane] : 0;
            int j = 0;
            for (; j + 8 <= cnt; j += 8) {
                float e[8]; int s[8];
#pragma unroll
                for (int u = 0; u < 8; u++) {
                    e[u] = __shfl_sync(0xffffffffu, ee, j + u);
                    s[u] = __shfl_sync(0xffffffffu, ss, j + u);
                }
                float4 hv[8];
#pragma unroll
                for (int u = 0; u < 8; u++)
                    hv[u] = ((const float4*)g_h)[(long)s[u] * 32 + lane];
#pragma unroll
                for (int u = 0; u < 8; u++) {
                    float w = __expf(e[u] - m);
                    den += w;
                    acc.x = fmaf(w, hv[u].x, acc.x);
                    acc.y = fmaf(w, hv[u].y, acc.y);
                    acc.z = fmaf(w, hv[u].z, acc.z);
                    acc.w = fmaf(w, hv[u].w, acc.w);
                }
            }
            for (; j < cnt; j++) {
                float e = __shfl_sync(0xffffffffu, ee, j);
                int s = __shfl_sync(0xffffffffu, ss, j);
                float w = __expf(e - m);
                den += w;
                float4 hv = ((const float4*)g_h)[(long)s * 32 + lane];
                acc.x = fmaf(w, hv.x, acc.x);
                acc.y = fmaf(w, hv.y, acc.y);
                acc.z = fmaf(w, hv.z, acc.z);
                acc.w = fmaf(w, hv.w, acc.w);
            }
        }
        float inv = 1.f / fmaxf(den, 1e-16f);
        float4 bg = ((const float4*)b_gat)[lane];
        float4 o;
        o.x = fmaxf(fmaf(acc.x, inv, bg.x), 0.f);
        o.y = fmaxf(fmaf(acc.y, inv, bg.y), 0.f);
        o.z = fmaxf(fmaf(acc.z, inv, bg.z), 0.f);
        o.w = fmaxf(fmaf(acc.w, inv, bg.w), 0.f);
        ((float4*)g_h0)[(long)n * 32 + lane] = o;

        int c0 = lane * 4;
        atomicAdd(&s_sum[c0 + 0], o.x); atomicAdd(&s_sq[c0 + 0], o.x * o.x);
        atomicAdd(&s_sum[c0 + 1], o.y); atomicAdd(&s_sq[c0 + 1], o.y * o.y);
        atomicAdd(&s_sum[c0 + 2], o.z); atomicAdd(&s_sq[c0 + 2], o.z * o.z);
        atomicAdd(&s_sum[c0 + 3], o.w); atomicAdd(&s_sq[c0 + 3], o.w * o.w);
    }
    __syncthreads();
    if (tid < HH) {
        atomicAdd(&g_stats0[tid], s_sum[tid]);
        atomicAdd(&g_stats0[HH + tid], s_sq[tid]);
    }
}

// ---------------- final head (+inlined bn2 finalize) ----------------
__global__ void k_final(const float* __restrict__ h2,
                        const float* __restrict__ stats2,
                        const float* __restrict__ g2, const float* __restrict__ beta2,
                        const float* __restrict__ W3, const float* __restrict__ b3,
                        float* __restrict__ out) {
    __shared__ float W3s[HH * AA];
    __shared__ float b3s[AA];
    __shared__ float s_scale[HH];
    __shared__ float s_shift[HH];
    int t = threadIdx.x; // 256
    for (int i = t; i < HH * AA; i += 256) W3s[i] = W3[i];
    if (t < AA) b3s[t] = b3[t];
    if (t < HH) {
        float mu = stats2[t] / (float)NN;
        float var = stats2[HH + t] / (float)NN - mu * mu;
        float sc = g2[t] * rsqrtf(var + 1e-5f);
        s_scale[t] = sc;
        s_shift[t] = beta2[t] - mu * sc;
    }
    __syncthreads();
    int lane = t & 31;
    int n = blockIdx.x * 8 + (t >> 5);
    if (n >= NN) return;
    float hreg[4];
#pragma unroll
    for (int j = 0; j < 4; j++) {
        int c = j * 32 + lane;
        hreg[j] = fmaf(h2[(long)n * HH + c], s_scale[c], s_shift[c]);
    }
    float acc = b3s[lane];
#pragma unroll
    for (int k = 0; k < HH; k++) {
        float hv = __shfl_sync(0xffffffffu, hreg[k >> 5], k & 31);
        acc = fmaf(hv, W3s[k * AA + lane], acc);
    }
    float mx = acc;
#pragma unroll
    for (int o = 16; o; o >>= 1) mx = fmaxf(mx, __shfl_xor_sync(0xffffffffu, mx, o));
    float p = __expf(acc - mx);
    float s = p;
#pragma unroll
    for (int o = 16; o; o >>= 1) s += __shfl_xor_sync(0xffffffffu, s, o);
    out[(long)n * AA + lane] = p / s;
}

// ---------------- launch ----------------
extern "C" void kernel_launch(void* const* d_in, const int* in_sizes, int n_in,
                              void* d_out, int out_size) {
    const float* x     = (const float*)d_in[0];
    const void*  ei    = d_in[1];
    const float* W     = (const float*)d_in[2];
    const float* a_src = (const float*)d_in[3];
    const float* a_dst = (const float*)d_in[4];
    const float* b_gat = (const float*)d_in[5];
    const float* g0    = (const float*)d_in[6];
    const float* beta0 = (const float*)d_in[7];
    const float* W1    = (const float*)d_in[8];
    const float* b1    = (const float*)d_in[9];
    const float* W2    = (const float*)d_in[10];
    const float* b2    = (const float*)d_in[11];
    const float* g2    = (const float*)d_in[12];
    const float* beta2 = (const float*)d_in[13];
    const float* W3    = (const float*)d_in[14];
    const float* b3    = (const float*)d_in[15];
    float* out = (float*)d_out;

    float *p_h, *p_h0, *p_h2, *p_stats0, *p_stats2;
    uint2 *p_bw;
    cudaGetSymbolAddress((void**)&p_h, g_h);
    cudaGetSymbolAddress((void**)&p_h0, g_h0);
    cudaGetSymbolAddress((void**)&p_h2, g_h2);
    cudaGetSymbolAddress((void**)&p_stats0, g_stats0);
    cudaGetSymbolAddress((void**)&p_stats2, g_stats2);
    cudaGetSymbolAddress((void**)&p_bw, g_Bw);

    const int gemmGrid = (NN + GBM - 1) / GBM;  // 782
    const int SMEM_GEMM = (16 * ASROW + 16 * BSROW) * (int)sizeof(uint2);              // 25600
    const int SMEM_FC   = (16 * ASROW + 16 * BSROW + 64 * ASROW) * (int)sizeof(uint2); // 60416

    static cudaStream_t s1 = nullptr;
    static cudaEvent_t evFork = nullptr, evJoin = nullptr;
    if (!s1) {
        cudaFuncSetAttribute(k_fc12, cudaFuncAttributeMaxDynamicSharedMemorySize, SMEM_FC);
        cudaStreamCreateWithFlags(&s1, cudaStreamNonBlocking);
        cudaEventCreateWithFlags(&evFork, cudaEventDisableTiming);
        cudaEventCreateWithFlags(&evJoin, cudaEventDisableTiming);
    }

    // stream 0: dtype detect only (rowcnt/stats zeroed by previous iteration's scatter)
    k_detect<<<1, 32>>>((const int*)ei);

    // fork: edge path + W1/W2 split on side stream
    cudaEventRecord(evFork, 0);
    cudaStreamWaitEvent(s1, evFork, 0);
    k_wa<<<DIN, 128, 0, s1>>>(W, a_src, a_dst);
    k_splitW12<<<64, 256, 0, s1>>>(W1, W2);
    k_hist<<<(EE + 255) / 256, 256, 0, s1>>>(ei);
    k_edot<<<(NN + 7) / 8, 256, 0, s1>>>(x);
    k_scan1<<<NB_SCAN, 256, 0, s1>>>();
    k_scan2<<<1, 256, 0, s1>>>();
    k_scan3<<<NB_SCAN, 256, 0, s1>>>();
    k_scatter<<<(EE + 255) / 256, 256, 0, s1>>>(ei);
    cudaEventRecord(evJoin, s1);

    // stream 0 meanwhile: W split + GEMM1 (h = x@W)
    k_splitW0<<<64, 256>>>(W);
    k_gemm_bf16<<<gemmGrid, 256, SMEM_GEMM>>>(x, p_bw, p_h, NN, DIN);

    // join: agg needs CSR (s1) + g_h (stream 0)
    cudaStreamWaitEvent(0, evJoin, 0);
    k_agg<<<(NN + 7) / 8, 256>>>(b_gat);

    // fused fc1 + fc2 (inlined bn0 finalize, +bn2 stats)
    k_fc12<<<gemmGrid, 256, SMEM_FC>>>(p_h0, p_bw + OFF_W1, p_bw + OFF_W2, p_h2, NN,
                                       p_stats0, g0, beta0, b1, b2, p_stats2);

    // final head (inlined bn2 finalize)
    k_final<<<(NN + 7) / 8, 256>>>(p_h2, p_stats2, g2, beta2, W3, b3, out);
}